// round 4
// baseline (speedup 1.0000x reference)
#include <cuda_runtime.h>
#include <math.h>

#define NN 20000
#define EE 320000
#define MMX (EE + NN)

// ---------------- scratch ----------------
__device__ float g_h[NN * 512];
__device__ float g_out[NN * 512];
__device__ float g_xa[NN * 128];
__device__ float g_xb[NN * 128];
__device__ float g_s[NN * 4];            // src scores (per head)
__device__ float g_d[NN * 4];            // dst scores (per head)
__device__ unsigned int g_m[NN * 4];     // segment max (order-preserving uint key)
__device__ float g_sum[NN * 4];          // segment exp-sum
__device__ float g_p[MMX * 4];           // per-edge exp values
__device__ int g_esrc[MMX];
__device__ int g_edst[MMX];
__device__ float g_h2[NN * 3];
__device__ float g_out2[NN * 3];

// ---------------- accurate exp/expm1/elu ----------------
__device__ __forceinline__ float exp_acc(float x) {
    x = fminf(fmaxf(x, -87.0f), 87.0f);
    float kf = rintf(__fmul_rn(x, 1.4426950408889634f));
    float r = __fmaf_rn(kf, -0.69314718246459960938f, x);
    r = __fmaf_rn(kf, 1.9046542743622637e-9f, r);
    float p = 1.9841269841269841e-4f;
    p = __fmaf_rn(p, r, 1.3888888888888889e-3f);
    p = __fmaf_rn(p, r, 8.3333333333333332e-3f);
    p = __fmaf_rn(p, r, 4.1666666666666664e-2f);
    p = __fmaf_rn(p, r, 1.6666666666666666e-1f);
    p = __fmaf_rn(p, r, 0.5f);
    p = __fmaf_rn(p, r, 1.0f);
    p = __fmaf_rn(p, r, 1.0f);
    int ik = (int)kf;
    float s = __int_as_float((ik + 127) << 23);
    return __fmul_rn(p, s);
}
__device__ __forceinline__ float expm1_acc(float x) {
    if (x < -0.34657359f) return __fadd_rn(exp_acc(x), -1.0f);
    float p = 1.9841269841269841e-4f;
    p = __fmaf_rn(p, x, 1.3888888888888889e-3f);
    p = __fmaf_rn(p, x, 8.3333333333333332e-3f);
    p = __fmaf_rn(p, x, 4.1666666666666664e-2f);
    p = __fmaf_rn(p, x, 1.6666666666666666e-1f);
    p = __fmaf_rn(p, x, 0.5f);
    p = __fmaf_rn(p, x, 1.0f);
    return __fmul_rn(p, x);
}
__device__ __forceinline__ float elu_acc(float x) {
    return x > 0.f ? x : expm1_acc(x);
}
__device__ __forceinline__ float lrelu(float x) {
    return x >= 0.f ? x : 0.2f * x;
}

// ---------------- order-preserving float<->uint key for atomicMax ----------------
__device__ __forceinline__ unsigned int fkey(float f) {
    unsigned int u = __float_as_uint(f);
    return (u & 0x80000000u) ? ~u : (u | 0x80000000u);
}
__device__ __forceinline__ float funkey(unsigned int u) {
    return (u & 0x80000000u) ? __uint_as_float(u & 0x7FFFFFFFu) : __uint_as_float(~u);
}

// ---------------- edge list ----------------
__global__ void k_edges(const int* __restrict__ ei, int e, int m) {
    int i = blockIdx.x * blockDim.x + threadIdx.x;
    if (i >= m) return;
    if (i < e) { g_esrc[i] = ei[i]; g_edst[i] = ei[e + i]; }
    else       { g_esrc[i] = i - e; g_edst[i] = i - e; }
}

// ---------------- clears ----------------
__global__ void k_clear512(int n) {
    int i = blockIdx.x * blockDim.x + threadIdx.x;
    if (i < n * 512) g_out[i] = 0.f;
    if (i < n * 4) { g_sum[i] = 0.f; g_m[i] = 0u; }
}
__global__ void k_clear2(int n) {
    int i = blockIdx.x * blockDim.x + threadIdx.x;
    if (i < n * 3) g_out2[i] = 0.f;
    if (i < n) { g_sum[i] = 0.f; g_m[i] = 0u; }
}

// ---------------- h kernels ----------------
__global__ void k_h_l0(const float* __restrict__ x, const float* __restrict__ W, int n) {
    int tid = blockIdx.x * blockDim.x + threadIdx.x;
    if (tid >= n * 512) return;
    int v = tid >> 9, j = tid & 511;
    g_h[tid] = x[2 * v] * W[2 * j] + x[2 * v + 1] * W[2 * j + 1];
}
__global__ void k_h_l1(const float* __restrict__ W, int n) {
    int tid = blockIdx.x * blockDim.x + threadIdx.x;
    if (tid >= n * 512) return;
    int v = tid >> 9, j = tid & 511;
    const float* xr = &g_xa[(size_t)v * 128];
    const float* wr = &W[(size_t)j * 128];
    float acc = 0.f;
    for (int k = 0; k < 128; k++) acc = __fmaf_rn(xr[k], wr[k], acc);
    g_h[tid] = acc;
}
__global__ void k_h_l2(const float* __restrict__ W, int n) {
    int tid = blockIdx.x * blockDim.x + threadIdx.x;
    if (tid >= n * 3) return;
    int v = tid / 3, o = tid - v * 3;
    const float* xr = &g_xb[(size_t)v * 128];
    const float* wr = &W[(size_t)o * 128];
    float acc = 0.f;
    for (int k = 0; k < 128; k++) acc = __fmaf_rn(xr[k], wr[k], acc);
    g_h2[tid] = acc;
}

// ---------------- score kernels ----------------
__global__ void k_score(const float* __restrict__ as_, const float* __restrict__ ad_, int n) {
    int tid = blockIdx.x * blockDim.x + threadIdx.x;
    if (tid >= n * 4) return;
    int v = tid >> 2, hd = tid & 3;
    const float* hr = &g_h[(size_t)v * 512 + hd * 128];
    const float* ar = &as_[hd * 128];
    const float* dr = &ad_[hd * 128];
    float s = 0.f, d = 0.f;
    for (int c = 0; c < 128; c++) { s = __fmaf_rn(hr[c], ar[c], s); d = __fmaf_rn(hr[c], dr[c], d); }
    g_s[tid] = s;
    g_d[tid] = d;
}
__global__ void k_score2(const float* __restrict__ as_, const float* __restrict__ ad_, int n) {
    int v = blockIdx.x * blockDim.x + threadIdx.x;
    if (v >= n) return;
    float s = 0.f, d = 0.f;
    for (int o = 0; o < 3; o++) {
        s = __fmaf_rn(g_h2[v * 3 + o], as_[o], s);
        d = __fmaf_rn(g_h2[v * 3 + o], ad_[o], d);
    }
    g_s[v] = s;
    g_d[v] = d;
}

// ---------------- segment max ----------------
__global__ void k_maxk(int m) {
    int tid = blockIdx.x * blockDim.x + threadIdx.x;
    if (tid >= m * 4) return;
    int i = tid >> 2, hd = tid & 3;
    int src = g_esrc[i], dst = g_edst[i];
    float l = lrelu(g_s[src * 4 + hd] + g_d[dst * 4 + hd]);
    atomicMax(&g_m[dst * 4 + hd], fkey(l));
}
__global__ void k_max2(int m) {
    int i = blockIdx.x * blockDim.x + threadIdx.x;
    if (i >= m) return;
    float l = lrelu(g_s[g_esrc[i]] + g_d[g_edst[i]]);
    atomicMax(&g_m[g_edst[i]], fkey(l));
}

// ---------------- exp + segment sum ----------------
__global__ void k_expsum(int m) {
    int tid = blockIdx.x * blockDim.x + threadIdx.x;
    if (tid >= m * 4) return;
    int i = tid >> 2, hd = tid & 3;
    int src = g_esrc[i], dst = g_edst[i];
    float l = lrelu(g_s[src * 4 + hd] + g_d[dst * 4 + hd]);
    float p = exp_acc(l - funkey(g_m[dst * 4 + hd]));
    g_p[i * 4 + hd] = p;
    atomicAdd(&g_sum[dst * 4 + hd], p);
}
__global__ void k_expsum2(int m) {
    int i = blockIdx.x * blockDim.x + threadIdx.x;
    if (i >= m) return;
    int dst = g_edst[i];
    float l = lrelu(g_s[g_esrc[i]] + g_d[dst]);
    float p = exp_acc(l - funkey(g_m[dst]));
    g_p[i] = p;
    atomicAdd(&g_sum[dst], p);
}

// ---------------- scatter: out[dst] += p * h[src] ----------------
__global__ void k_scat(int m) {
    int tid = blockIdx.x * blockDim.x + threadIdx.x;
    if (tid >= m * 128) return;
    int i = tid >> 7, c = tid & 127;
    int src = g_esrc[i], dst = g_edst[i];
#pragma unroll
    for (int hd = 0; hd < 4; hd++) {
        float p = g_p[i * 4 + hd];
        atomicAdd(&g_out[(size_t)dst * 512 + hd * 128 + c],
                  p * g_h[(size_t)src * 512 + hd * 128 + c]);
    }
}
__global__ void k_scat2(int m) {
    int i = blockIdx.x * blockDim.x + threadIdx.x;
    if (i >= m) return;
    int src = g_esrc[i], dst = g_edst[i];
    float p = g_p[i];
#pragma unroll
    for (int o = 0; o < 3; o++)
        atomicAdd(&g_out2[dst * 3 + o], p * g_h2[src * 3 + o]);
}

// ---------------- finalize (mean heads + bias + ELU + BN) ----------------
__global__ void k_fin(const float* __restrict__ bias,
                      const float* __restrict__ bng, const float* __restrict__ bnb,
                      const float* __restrict__ bnm, const float* __restrict__ bnv,
                      int outsel, int n) {
    int tid = blockIdx.x * blockDim.x + threadIdx.x;
    if (tid >= n * 128) return;
    int v = tid >> 7, c = tid & 127;
    float acc = 0.f;
#pragma unroll
    for (int hd = 0; hd < 4; hd++) {
        float denom = __fadd_rn(g_sum[v * 4 + hd], 1e-16f);
        acc = __fadd_rn(acc, __fdiv_rn(g_out[(size_t)v * 512 + hd * 128 + c], denom));
    }
    float val = __fmul_rn(acc, 0.25f);
    val = __fadd_rn(val, bias[c]);
    val = elu_acc(val);
    float inv = __frsqrt_rn(__fadd_rn(bnv[c], 1e-5f));
    val = __fadd_rn(__fmul_rn(__fmul_rn(__fsub_rn(val, bnm[c]), inv), bng[c]), bnb[c]);
    (outsel ? g_xb : g_xa)[(size_t)v * 128 + c] = val;
}

// ---------------- layer-2 finalize + ODE epilogue ----------------
__global__ void k_epi(const float* __restrict__ b2,
                      const float* __restrict__ kk, const float* __restrict__ dd,
                      const float* __restrict__ t00, const float* __restrict__ u00,
                      const float* __restrict__ t, float* __restrict__ out, int n) {
    int v = blockIdx.x * blockDim.x + threadIdx.x;
    if (v >= n) return;
    float denom = __fadd_rn(g_sum[v], 1e-16f);
    float ar  = elu_acc(__fadd_rn(__fdiv_rn(g_out2[v * 3 + 0], denom), b2[0]));
    float gam = elu_acc(__fadd_rn(__fdiv_rn(g_out2[v * 3 + 1], denom), b2[1]));
    float bet = elu_acc(__fadd_rn(__fdiv_rn(g_out2[v * 3 + 2], denom), b2[2]));

    float tt = t[v];
    float K = kk[0], D = dd[0], T0 = t00[0], U0 = u00[0];

    float z = __fmul_rn(K, __fsub_rn(__fsub_rn(tt, T0), D));
    float S = __fdiv_rn(1.0f, __fadd_rn(1.0f, exp_acc(-z)));
    float oneMS = __fsub_rn(1.0f, S);

    float eb  = exp_acc(__fmul_rn(-bet, tt));
    float eg  = exp_acc(__fmul_rn(-gam, tt));
    float tmt0 = __fsub_rn(tt, T0);
    float ebs = exp_acc(__fmul_rn(-bet, tmt0));
    float egs = exp_acc(__fmul_rn(-gam, tmt0));
    float ab = __fdiv_rn(ar, bet);
    float ag = __fdiv_rn(ar, gam);

    float tu = __fadd_rn(
                 __fadd_rn(__fmul_rn(__fmul_rn(ab, __fsub_rn(1.0f, eb)), oneMS),
                           __fmul_rn(ab, S)),
                 __fmul_rn(__fsub_rn(__fmul_rn(U0, ebs), ab), S));

    float gmb = __fsub_rn(gam, bet);
    float term1 = __fadd_rn(__fmul_rn(ag, __fsub_rn(1.0f, eg)),
                            __fmul_rn(__fdiv_rn(ar, gmb), __fsub_rn(eg, eb)));
    float term3 = __fmul_rn(__fmul_rn(__fdiv_rn(__fmul_rn(bet, U0), gmb),
                                      __fsub_rn(egs, ebs)), S);
    float ts = __fadd_rn(__fadd_rn(__fmul_rn(term1, oneMS), __fmul_rn(ag, S)), term3);

    out[v] = tu;
    out[n + v] = ts;
}

// ---------------- launch ----------------
extern "C" void kernel_launch(void* const* d_in, const int* in_sizes, int n_in,
                              void* d_out, int out_size) {
    int off = (n_in >= 28) ? 0 : -1;
    const float* x    = (const float*)d_in[0];
    const int*   ei   = (const int*)d_in[1];
    const float* W0   = (const float*)d_in[3 + off];
    const float* as0  = (const float*)d_in[4 + off];
    const float* ad0  = (const float*)d_in[5 + off];
    const float* b0   = (const float*)d_in[6 + off];
    const float* W1   = (const float*)d_in[7 + off];
    const float* as1  = (const float*)d_in[8 + off];
    const float* ad1  = (const float*)d_in[9 + off];
    const float* b1   = (const float*)d_in[10 + off];
    const float* W2   = (const float*)d_in[11 + off];
    const float* as2  = (const float*)d_in[12 + off];
    const float* ad2  = (const float*)d_in[13 + off];
    const float* b2   = (const float*)d_in[14 + off];
    const float* bng0 = (const float*)d_in[15 + off];
    const float* bnb0 = (const float*)d_in[16 + off];
    const float* bnm0 = (const float*)d_in[17 + off];
    const float* bnv0 = (const float*)d_in[18 + off];
    const float* bng1 = (const float*)d_in[19 + off];
    const float* bnb1 = (const float*)d_in[20 + off];
    const float* bnm1 = (const float*)d_in[21 + off];
    const float* bnv1 = (const float*)d_in[22 + off];
    const float* kk   = (const float*)d_in[23 + off];
    const float* dd   = (const float*)d_in[24 + off];
    const float* t00  = (const float*)d_in[25 + off];
    const float* u00  = (const float*)d_in[26 + off];
    const float* t    = (const float*)d_in[27 + off];
    float* out = (float*)d_out;

    int n = in_sizes[0] / 2;
    int e = in_sizes[1] / 2;
    int m = e + n;

    const int B = 256;
    auto nb = [](long long x, int b) { return (int)((x + b - 1) / b); };

    k_edges<<<nb(m, B), B>>>(ei, e, m);

    // ---- layer 0 ----
    k_clear512<<<nb((long long)n * 512, B), B>>>(n);
    k_h_l0<<<nb((long long)n * 512, B), B>>>(x, W0, n);
    k_score<<<nb(n * 4, B), B>>>(as0, ad0, n);
    k_maxk<<<nb((long long)m * 4, B), B>>>(m);
    k_expsum<<<nb((long long)m * 4, B), B>>>(m);
    k_scat<<<nb((long long)m * 128, B), B>>>(m);
    k_fin<<<nb((long long)n * 128, B), B>>>(b0, bng0, bnb0, bnm0, bnv0, 0, n);

    // ---- layer 1 ----
    k_clear512<<<nb((long long)n * 512, B), B>>>(n);
    k_h_l1<<<nb((long long)n * 512, B), B>>>(W1, n);
    k_score<<<nb(n * 4, B), B>>>(as1, ad1, n);
    k_maxk<<<nb((long long)m * 4, B), B>>>(m);
    k_expsum<<<nb((long long)m * 4, B), B>>>(m);
    k_scat<<<nb((long long)m * 128, B), B>>>(m);
    k_fin<<<nb((long long)n * 128, B), B>>>(b1, bng1, bnb1, bnm1, bnv1, 1, n);

    // ---- layer 2 + epilogue ----
    k_clear2<<<nb((long long)n * 3, B), B>>>(n);
    k_h_l2<<<nb((long long)n * 3, B), B>>>(W2, n);
    k_score2<<<nb(n, B), B>>>(as2, ad2, n);
    k_max2<<<nb(m, B), B>>>(m);
    k_expsum2<<<nb(m, B), B>>>(m);
    k_scat2<<<nb(m, B), B>>>(m);
    k_epi<<<nb(n, B), B>>>(b2, kk, dd, t00, u00, t, out, n);
}

// round 5
// speedup vs baseline: 1.0103x; 1.0103x over previous
#include <cuda_runtime.h>
#include <math.h>

#define NN 20000
#define EE 320000
#define MMX (EE + NN)
#define FULL 0xffffffffu

// ---------------- scratch ----------------
__device__ float g_h[NN * 512];
__device__ float g_xa[NN * 128];
__device__ float g_xb[NN * 128];
__device__ float g_s[NN * 4];            // src scores (per head)
__device__ float g_d[NN * 4];            // dst scores (per head)
__device__ unsigned int g_m[NN * 4];     // segment max (order-preserving uint key)
__device__ float g_sum[NN * 4];          // segment exp-sum
__device__ float g_p[MMX * 4];           // per-edge exp values
__device__ int g_esrc[MMX];
__device__ int g_edst[MMX];
__device__ float g_h2[NN * 3];
__device__ float g_out2[NN * 3];
// CSR by dst (stores EDGE IDS)
__device__ int g_deg[NN];
__device__ int g_rowptr[NN + 1];
__device__ int g_cursor[NN];
__device__ int g_csr[MMX];

// ---------------- accurate exp/expm1/elu ----------------
__device__ __forceinline__ float exp_acc(float x) {
    x = fminf(fmaxf(x, -87.0f), 87.0f);
    float kf = rintf(__fmul_rn(x, 1.4426950408889634f));
    float r = __fmaf_rn(kf, -0.69314718246459960938f, x);
    r = __fmaf_rn(kf, 1.9046542743622637e-9f, r);
    float p = 1.9841269841269841e-4f;
    p = __fmaf_rn(p, r, 1.3888888888888889e-3f);
    p = __fmaf_rn(p, r, 8.3333333333333332e-3f);
    p = __fmaf_rn(p, r, 4.1666666666666664e-2f);
    p = __fmaf_rn(p, r, 1.6666666666666666e-1f);
    p = __fmaf_rn(p, r, 0.5f);
    p = __fmaf_rn(p, r, 1.0f);
    p = __fmaf_rn(p, r, 1.0f);
    int ik = (int)kf;
    float s = __int_as_float((ik + 127) << 23);
    return __fmul_rn(p, s);
}
__device__ __forceinline__ float expm1_acc(float x) {
    if (x < -0.34657359f) return __fadd_rn(exp_acc(x), -1.0f);
    float p = 1.9841269841269841e-4f;
    p = __fmaf_rn(p, x, 1.3888888888888889e-3f);
    p = __fmaf_rn(p, x, 8.3333333333333332e-3f);
    p = __fmaf_rn(p, x, 4.1666666666666664e-2f);
    p = __fmaf_rn(p, x, 1.6666666666666666e-1f);
    p = __fmaf_rn(p, x, 0.5f);
    p = __fmaf_rn(p, x, 1.0f);
    return __fmul_rn(p, x);
}
__device__ __forceinline__ float elu_acc(float x) {
    return x > 0.f ? x : expm1_acc(x);
}
__device__ __forceinline__ float lrelu(float x) {
    return x >= 0.f ? x : 0.2f * x;
}

// ---------------- order-preserving float<->uint key for atomicMax ----------------
__device__ __forceinline__ unsigned int fkey(float f) {
    unsigned int u = __float_as_uint(f);
    return (u & 0x80000000u) ? ~u : (u | 0x80000000u);
}
__device__ __forceinline__ float funkey(unsigned int u) {
    return (u & 0x80000000u) ? __uint_as_float(u & 0x7FFFFFFFu) : __uint_as_float(~u);
}

// ---------------- edge list ----------------
__global__ void k_edges(const int* __restrict__ ei, int e, int m) {
    int i = blockIdx.x * blockDim.x + threadIdx.x;
    if (i >= m) return;
    if (i < e) { g_esrc[i] = ei[i]; g_edst[i] = ei[e + i]; }
    else       { g_esrc[i] = i - e; g_edst[i] = i - e; }
}

// ---------------- CSR build (by dst, storing edge ids) ----------------
__global__ void k_zero(int n) {
    int i = blockIdx.x * blockDim.x + threadIdx.x;
    if (i < n) g_deg[i] = 0;
}
__global__ void k_count(int m) {
    int i = blockIdx.x * blockDim.x + threadIdx.x;
    if (i < m) atomicAdd(&g_deg[g_edst[i]], 1);
}
__global__ void k_scan(int n, int m) {
    __shared__ int part[512];
    int t = threadIdx.x;
    int chunk = (n + 511) / 512;
    int b0 = t * chunk;
    int b1 = min(b0 + chunk, n);
    int s = 0;
    for (int i = b0; i < b1; i++) s += g_deg[i];
    part[t] = s;
    __syncthreads();
    for (int off = 1; off < 512; off <<= 1) {
        int add = (t >= off) ? part[t - off] : 0;
        __syncthreads();
        part[t] += add;
        __syncthreads();
    }
    int run = (t == 0) ? 0 : part[t - 1];
    for (int i = b0; i < b1; i++) {
        g_rowptr[i] = run;
        g_cursor[i] = run;
        run += g_deg[i];
    }
    if (t == 0) g_rowptr[n] = m;
}
__global__ void k_fill(int m) {
    int i = blockIdx.x * blockDim.x + threadIdx.x;
    if (i < m) {
        int pos = atomicAdd(&g_cursor[g_edst[i]], 1);
        g_csr[pos] = i;   // edge id
    }
}

// ---------------- clears (softmax state only) ----------------
__global__ void k_clearS(int n) {
    int i = blockIdx.x * blockDim.x + threadIdx.x;
    if (i < n * 4) { g_sum[i] = 0.f; g_m[i] = 0u; }
}
__global__ void k_clear2(int n) {
    int i = blockIdx.x * blockDim.x + threadIdx.x;
    if (i < n * 3) g_out2[i] = 0.f;
    if (i < n) { g_sum[i] = 0.f; g_m[i] = 0u; }
}

// ---------------- h kernels ----------------
__global__ void k_h_l0(const float* __restrict__ x, const float* __restrict__ W, int n) {
    int tid = blockIdx.x * blockDim.x + threadIdx.x;
    if (tid >= n * 512) return;
    int v = tid >> 9, j = tid & 511;
    g_h[tid] = x[2 * v] * W[2 * j] + x[2 * v + 1] * W[2 * j + 1];
}
__global__ void k_h_l1(const float* __restrict__ W, int n) {
    int tid = blockIdx.x * blockDim.x + threadIdx.x;
    if (tid >= n * 512) return;
    int v = tid >> 9, j = tid & 511;
    const float* xr = &g_xa[(size_t)v * 128];
    const float* wr = &W[(size_t)j * 128];
    float acc = 0.f;
    for (int k = 0; k < 128; k++) acc = __fmaf_rn(xr[k], wr[k], acc);
    g_h[tid] = acc;
}
__global__ void k_h_l2(const float* __restrict__ W, int n) {
    int tid = blockIdx.x * blockDim.x + threadIdx.x;
    if (tid >= n * 3) return;
    int v = tid / 3, o = tid - v * 3;
    const float* xr = &g_xb[(size_t)v * 128];
    const float* wr = &W[(size_t)o * 128];
    float acc = 0.f;
    for (int k = 0; k < 128; k++) acc = __fmaf_rn(xr[k], wr[k], acc);
    g_h2[tid] = acc;
}

// ---------------- score kernels ----------------
__global__ void k_score(const float* __restrict__ as_, const float* __restrict__ ad_, int n) {
    int tid = blockIdx.x * blockDim.x + threadIdx.x;
    if (tid >= n * 4) return;
    int v = tid >> 2, hd = tid & 3;
    const float* hr = &g_h[(size_t)v * 512 + hd * 128];
    const float* ar = &as_[hd * 128];
    const float* dr = &ad_[hd * 128];
    float s = 0.f, d = 0.f;
    for (int c = 0; c < 128; c++) { s = __fmaf_rn(hr[c], ar[c], s); d = __fmaf_rn(hr[c], dr[c], d); }
    g_s[tid] = s;
    g_d[tid] = d;
}
__global__ void k_score2(const float* __restrict__ as_, const float* __restrict__ ad_, int n) {
    int v = blockIdx.x * blockDim.x + threadIdx.x;
    if (v >= n) return;
    float s = 0.f, d = 0.f;
    for (int o = 0; o < 3; o++) {
        s = __fmaf_rn(g_h2[v * 3 + o], as_[o], s);
        d = __fmaf_rn(g_h2[v * 3 + o], ad_[o], d);
    }
    g_s[v] = s;
    g_d[v] = d;
}

// ---------------- segment max ----------------
__global__ void k_maxk(int m) {
    int tid = blockIdx.x * blockDim.x + threadIdx.x;
    if (tid >= m * 4) return;
    int i = tid >> 2, hd = tid & 3;
    int src = g_esrc[i], dst = g_edst[i];
    float l = lrelu(g_s[src * 4 + hd] + g_d[dst * 4 + hd]);
    atomicMax(&g_m[dst * 4 + hd], fkey(l));
}
__global__ void k_max2(int m) {
    int i = blockIdx.x * blockDim.x + threadIdx.x;
    if (i >= m) return;
    float l = lrelu(g_s[g_esrc[i]] + g_d[g_edst[i]]);
    atomicMax(&g_m[g_edst[i]], fkey(l));
}

// ---------------- exp + segment sum ----------------
__global__ void k_expsum(int m) {
    int tid = blockIdx.x * blockDim.x + threadIdx.x;
    if (tid >= m * 4) return;
    int i = tid >> 2, hd = tid & 3;
    int src = g_esrc[i], dst = g_edst[i];
    float l = lrelu(g_s[src * 4 + hd] + g_d[dst * 4 + hd]);
    float p = exp_acc(l - funkey(g_m[dst * 4 + hd]));
    g_p[i * 4 + hd] = p;
    atomicAdd(&g_sum[dst * 4 + hd], p);
}
__global__ void k_expsum2(int m) {
    int i = blockIdx.x * blockDim.x + threadIdx.x;
    if (i >= m) return;
    int dst = g_edst[i];
    float l = lrelu(g_s[g_esrc[i]] + g_d[dst]);
    float p = exp_acc(l - funkey(g_m[dst]));
    g_p[i] = p;
    atomicAdd(&g_sum[dst], p);
}

// ---------------- NEW: warp-per-node CSR gather + finalize (layers 0/1) ----------------
__global__ void k_gath(const float* __restrict__ bias,
                       const float* __restrict__ bng, const float* __restrict__ bnb,
                       const float* __restrict__ bnm, const float* __restrict__ bnv,
                       int outsel, int n) {
    int v = (blockIdx.x * blockDim.x + threadIdx.x) >> 5;
    int lane = threadIdx.x & 31;
    if (v >= n) return;
    int beg = g_rowptr[v], end = g_rowptr[v + 1];

    // acc[hd*4 + j] accumulates channel c = lane*4 + j of head hd
    float acc[16];
#pragma unroll
    for (int i = 0; i < 16; i++) acc[i] = 0.f;

    for (int base = beg; base < end; base += 32) {
        int idx = base + lane;
        int sv = 0;
        float4 pv = make_float4(0.f, 0.f, 0.f, 0.f);
        if (idx < end) {
            int eid = g_csr[idx];
            sv = g_esrc[eid];
            pv = *(const float4*)&g_p[(size_t)eid * 4];
        }
        int cnt = min(32, end - base);
        for (int t = 0; t < cnt; t++) {
            int s = __shfl_sync(FULL, sv, t);
            float p0 = __shfl_sync(FULL, pv.x, t);
            float p1 = __shfl_sync(FULL, pv.y, t);
            float p2 = __shfl_sync(FULL, pv.z, t);
            float p3 = __shfl_sync(FULL, pv.w, t);
            const float4* hp = (const float4*)(g_h + (size_t)s * 512);
            float4 h0 = hp[lane];        // head 0, ch lane*4..+3
            float4 h1 = hp[32 + lane];   // head 1
            float4 h2 = hp[64 + lane];   // head 2
            float4 h3 = hp[96 + lane];   // head 3
            acc[0]  += h0.x * p0; acc[1]  += h0.y * p0; acc[2]  += h0.z * p0; acc[3]  += h0.w * p0;
            acc[4]  += h1.x * p1; acc[5]  += h1.y * p1; acc[6]  += h1.z * p1; acc[7]  += h1.w * p1;
            acc[8]  += h2.x * p2; acc[9]  += h2.y * p2; acc[10] += h2.z * p2; acc[11] += h2.w * p2;
            acc[12] += h3.x * p3; acc[13] += h3.y * p3; acc[14] += h3.z * p3; acc[15] += h3.w * p3;
        }
    }

    // denominators: exact atomic-computed segment sums (same values as passing R4)
    float d0 = __fadd_rn(g_sum[v * 4 + 0], 1e-16f);
    float d1 = __fadd_rn(g_sum[v * 4 + 1], 1e-16f);
    float d2 = __fadd_rn(g_sum[v * 4 + 2], 1e-16f);
    float d3 = __fadd_rn(g_sum[v * 4 + 3], 1e-16f);

    int c = lane * 4;
    float vals[4];
#pragma unroll
    for (int j = 0; j < 4; j++) {
        float a = 0.f;
        a = __fadd_rn(a, __fdiv_rn(acc[j],      d0));
        a = __fadd_rn(a, __fdiv_rn(acc[4 + j],  d1));
        a = __fadd_rn(a, __fdiv_rn(acc[8 + j],  d2));
        a = __fadd_rn(a, __fdiv_rn(acc[12 + j], d3));
        float val = __fmul_rn(a, 0.25f);
        val = __fadd_rn(val, bias[c + j]);
        val = elu_acc(val);
        float inv = __frsqrt_rn(__fadd_rn(bnv[c + j], 1e-5f));
        val = __fadd_rn(__fmul_rn(__fmul_rn(__fsub_rn(val, bnm[c + j]), inv), bng[c + j]), bnb[c + j]);
        vals[j] = val;
    }
    float* xout = outsel ? g_xb : g_xa;
    *(float4*)&xout[(size_t)v * 128 + c] = make_float4(vals[0], vals[1], vals[2], vals[3]);
}

// ---------------- layer-2 scatter (kept naive: tiny) ----------------
__global__ void k_scat2(int m) {
    int i = blockIdx.x * blockDim.x + threadIdx.x;
    if (i >= m) return;
    int src = g_esrc[i], dst = g_edst[i];
    float p = g_p[i];
#pragma unroll
    for (int o = 0; o < 3; o++)
        atomicAdd(&g_out2[dst * 3 + o], p * g_h2[src * 3 + o]);
}

// ---------------- layer-2 finalize + ODE epilogue ----------------
__global__ void k_epi(const float* __restrict__ b2,
                      const float* __restrict__ kk, const float* __restrict__ dd,
                      const float* __restrict__ t00, const float* __restrict__ u00,
                      const float* __restrict__ t, float* __restrict__ out, int n) {
    int v = blockIdx.x * blockDim.x + threadIdx.x;
    if (v >= n) return;
    float denom = __fadd_rn(g_sum[v], 1e-16f);
    float ar  = elu_acc(__fadd_rn(__fdiv_rn(g_out2[v * 3 + 0], denom), b2[0]));
    float gam = elu_acc(__fadd_rn(__fdiv_rn(g_out2[v * 3 + 1], denom), b2[1]));
    float bet = elu_acc(__fadd_rn(__fdiv_rn(g_out2[v * 3 + 2], denom), b2[2]));

    float tt = t[v];
    float K = kk[0], D = dd[0], T0 = t00[0], U0 = u00[0];

    float z = __fmul_rn(K, __fsub_rn(__fsub_rn(tt, T0), D));
    float S = __fdiv_rn(1.0f, __fadd_rn(1.0f, exp_acc(-z)));
    float oneMS = __fsub_rn(1.0f, S);

    float eb  = exp_acc(__fmul_rn(-bet, tt));
    float eg  = exp_acc(__fmul_rn(-gam, tt));
    float tmt0 = __fsub_rn(tt, T0);
    float ebs = exp_acc(__fmul_rn(-bet, tmt0));
    float egs = exp_acc(__fmul_rn(-gam, tmt0));
    float ab = __fdiv_rn(ar, bet);
    float ag = __fdiv_rn(ar, gam);

    float tu = __fadd_rn(
                 __fadd_rn(__fmul_rn(__fmul_rn(ab, __fsub_rn(1.0f, eb)), oneMS),
                           __fmul_rn(ab, S)),
                 __fmul_rn(__fsub_rn(__fmul_rn(U0, ebs), ab), S));

    float gmb = __fsub_rn(gam, bet);
    float term1 = __fadd_rn(__fmul_rn(ag, __fsub_rn(1.0f, eg)),
                            __fmul_rn(__fdiv_rn(ar, gmb), __fsub_rn(eg, eb)));
    float term3 = __fmul_rn(__fmul_rn(__fdiv_rn(__fmul_rn(bet, U0), gmb),
                                      __fsub_rn(egs, ebs)), S);
    float ts = __fadd_rn(__fadd_rn(__fmul_rn(term1, oneMS), __fmul_rn(ag, S)), term3);

    out[v] = tu;
    out[n + v] = ts;
}

// ---------------- launch ----------------
extern "C" void kernel_launch(void* const* d_in, const int* in_sizes, int n_in,
                              void* d_out, int out_size) {
    int off = (n_in >= 28) ? 0 : -1;
    const float* x    = (const float*)d_in[0];
    const int*   ei   = (const int*)d_in[1];
    const float* W0   = (const float*)d_in[3 + off];
    const float* as0  = (const float*)d_in[4 + off];
    const float* ad0  = (const float*)d_in[5 + off];
    const float* b0   = (const float*)d_in[6 + off];
    const float* W1   = (const float*)d_in[7 + off];
    const float* as1  = (const float*)d_in[8 + off];
    const float* ad1  = (const float*)d_in[9 + off];
    const float* b1   = (const float*)d_in[10 + off];
    const float* W2   = (const float*)d_in[11 + off];
    const float* as2  = (const float*)d_in[12 + off];
    const float* ad2  = (const float*)d_in[13 + off];
    const float* b2   = (const float*)d_in[14 + off];
    const float* bng0 = (const float*)d_in[15 + off];
    const float* bnb0 = (const float*)d_in[16 + off];
    const float* bnm0 = (const float*)d_in[17 + off];
    const float* bnv0 = (const float*)d_in[18 + off];
    const float* bng1 = (const float*)d_in[19 + off];
    const float* bnb1 = (const float*)d_in[20 + off];
    const float* bnm1 = (const float*)d_in[21 + off];
    const float* bnv1 = (const float*)d_in[22 + off];
    const float* kk   = (const float*)d_in[23 + off];
    const float* dd   = (const float*)d_in[24 + off];
    const float* t00  = (const float*)d_in[25 + off];
    const float* u00  = (const float*)d_in[26 + off];
    const float* t    = (const float*)d_in[27 + off];
    float* out = (float*)d_out;

    int n = in_sizes[0] / 2;
    int e = in_sizes[1] / 2;
    int m = e + n;

    const int B = 256;
    auto nb = [](long long x, int b) { return (int)((x + b - 1) / b); };
    int nwb = nb((long long)n * 32, B);   // warp-per-node grids

    k_edges<<<nb(m, B), B>>>(ei, e, m);

    // CSR (dst-indexed, edge ids)
    k_zero<<<nb(n, B), B>>>(n);
    k_count<<<nb(m, B), B>>>(m);
    k_scan<<<1, 512>>>(n, m);
    k_fill<<<nb(m, B), B>>>(m);

    // ---- layer 0 ----
    k_clearS<<<nb(n * 4, B), B>>>(n);
    k_h_l0<<<nb((long long)n * 512, B), B>>>(x, W0, n);
    k_score<<<nb(n * 4, B), B>>>(as0, ad0, n);
    k_maxk<<<nb((long long)m * 4, B), B>>>(m);
    k_expsum<<<nb((long long)m * 4, B), B>>>(m);
    k_gath<<<nwb, B>>>(b0, bng0, bnb0, bnm0, bnv0, 0, n);

    // ---- layer 1 ----
    k_clearS<<<nb(n * 4, B), B>>>(n);
    k_h_l1<<<nb((long long)n * 512, B), B>>>(W1, n);
    k_score<<<nb(n * 4, B), B>>>(as1, ad1, n);
    k_maxk<<<nb((long long)m * 4, B), B>>>(m);
    k_expsum<<<nb((long long)m * 4, B), B>>>(m);
    k_gath<<<nwb, B>>>(b1, bng1, bnb1, bnm1, bnv1, 1, n);

    // ---- layer 2 + epilogue ----
    k_clear2<<<nb((long long)n * 3, B), B>>>(n);
    k_h_l2<<<nb((long long)n * 3, B), B>>>(W2, n);
    k_score2<<<nb(n, B), B>>>(as2, ad2, n);
    k_max2<<<nb(m, B), B>>>(m);
    k_expsum2<<<nb(m, B), B>>>(m);
    k_scat2<<<nb(m, B), B>>>(m);
    k_epi<<<nb(n, B), B>>>(b2, kk, dd, t00, u00, t, out, n);
}

// round 6
// speedup vs baseline: 12.8826x; 12.7509x over previous
#include <cuda_runtime.h>
#include <math.h>

#define NN 20000
#define EE 320000
#define MMX (EE + NN)
#define FULL 0xffffffffu

// ---------------- scratch ----------------
__device__ float g_h[NN * 512];
__device__ float g_xa[NN * 128];
__device__ float g_xb[NN * 128];
__device__ float g_s[NN * 4];            // src scores (per head)
__device__ float g_d[NN * 4];            // dst scores (per head)
__device__ unsigned int g_m[NN * 4];     // segment max (order-preserving uint key)
__device__ float g_sum[NN * 4];          // segment exp-sum
__device__ float g_p[MMX * 4];           // per-edge exp values
__device__ int g_esrc[MMX];
__device__ int g_edst[MMX];
__device__ float g_h2[NN * 3];
__device__ float g_out2[NN * 3];
// CSR by dst (stores EDGE IDS)
__device__ int g_deg[NN];
__device__ int g_rowptr[NN + 1];
__device__ int g_cursor[NN];
__device__ int g_csr[MMX];

// ---------------- accurate exp/expm1/elu ----------------
__device__ __forceinline__ float exp_acc(float x) {
    x = fminf(fmaxf(x, -87.0f), 87.0f);
    float kf = rintf(__fmul_rn(x, 1.4426950408889634f));
    float r = __fmaf_rn(kf, -0.69314718246459960938f, x);
    r = __fmaf_rn(kf, 1.9046542743622637e-9f, r);
    float p = 1.9841269841269841e-4f;
    p = __fmaf_rn(p, r, 1.3888888888888889e-3f);
    p = __fmaf_rn(p, r, 8.3333333333333332e-3f);
    p = __fmaf_rn(p, r, 4.1666666666666664e-2f);
    p = __fmaf_rn(p, r, 1.6666666666666666e-1f);
    p = __fmaf_rn(p, r, 0.5f);
    p = __fmaf_rn(p, r, 1.0f);
    p = __fmaf_rn(p, r, 1.0f);
    int ik = (int)kf;
    float s = __int_as_float((ik + 127) << 23);
    return __fmul_rn(p, s);
}
__device__ __forceinline__ float expm1_acc(float x) {
    if (x < -0.34657359f) return __fadd_rn(exp_acc(x), -1.0f);
    float p = 1.9841269841269841e-4f;
    p = __fmaf_rn(p, x, 1.3888888888888889e-3f);
    p = __fmaf_rn(p, x, 8.3333333333333332e-3f);
    p = __fmaf_rn(p, x, 4.1666666666666664e-2f);
    p = __fmaf_rn(p, x, 1.6666666666666666e-1f);
    p = __fmaf_rn(p, x, 0.5f);
    p = __fmaf_rn(p, x, 1.0f);
    return __fmul_rn(p, x);
}
__device__ __forceinline__ float elu_acc(float x) {
    return x > 0.f ? x : expm1_acc(x);
}
__device__ __forceinline__ float lrelu(float x) {
    return x >= 0.f ? x : 0.2f * x;
}

// ---------------- order-preserving float<->uint key for atomicMax ----------------
__device__ __forceinline__ unsigned int fkey(float f) {
    unsigned int u = __float_as_uint(f);
    return (u & 0x80000000u) ? ~u : (u | 0x80000000u);
}
__device__ __forceinline__ float funkey(unsigned int u) {
    return (u & 0x80000000u) ? __uint_as_float(u & 0x7FFFFFFFu) : __uint_as_float(~u);
}

// ---------------- edge list ----------------
__global__ void k_edges(const int* __restrict__ ei, int e, int m) {
    int i = blockIdx.x * blockDim.x + threadIdx.x;
    if (i >= m) return;
    if (i < e) { g_esrc[i] = ei[i]; g_edst[i] = ei[e + i]; }
    else       { g_esrc[i] = i - e; g_edst[i] = i - e; }
}

// ---------------- CSR build (by dst, storing edge ids) ----------------
__global__ void k_zero(int n) {
    int i = blockIdx.x * blockDim.x + threadIdx.x;
    if (i < n) g_deg[i] = 0;
}
__global__ void k_count(int m) {
    int i = blockIdx.x * blockDim.x + threadIdx.x;
    if (i < m) atomicAdd(&g_deg[g_edst[i]], 1);
}
__global__ void k_scan(int n, int m) {
    __shared__ int part[512];
    int t = threadIdx.x;
    int chunk = (n + 511) / 512;
    int b0 = t * chunk;
    int b1 = min(b0 + chunk, n);
    int s = 0;
    for (int i = b0; i < b1; i++) s += g_deg[i];
    part[t] = s;
    __syncthreads();
    for (int off = 1; off < 512; off <<= 1) {
        int add = (t >= off) ? part[t - off] : 0;
        __syncthreads();
        part[t] += add;
        __syncthreads();
    }
    int run = (t == 0) ? 0 : part[t - 1];
    for (int i = b0; i < b1; i++) {
        g_rowptr[i] = run;
        g_cursor[i] = run;
        run += g_deg[i];
    }
    if (t == 0) g_rowptr[n] = m;
}
__global__ void k_fill(int m) {
    int i = blockIdx.x * blockDim.x + threadIdx.x;
    if (i < m) {
        int pos = atomicAdd(&g_cursor[g_edst[i]], 1);
        g_csr[pos] = i;   // edge id
    }
}

// ---------------- clears (softmax state only) ----------------
__global__ void k_clearS(int n) {
    int i = blockIdx.x * blockDim.x + threadIdx.x;
    if (i < n * 4) { g_sum[i] = 0.f; g_m[i] = 0u; }
}
__global__ void k_clear2(int n) {
    int i = blockIdx.x * blockDim.x + threadIdx.x;
    if (i < n * 3) g_out2[i] = 0.f;
    if (i < n) { g_sum[i] = 0.f; g_m[i] = 0u; }
}

// ---------------- h kernels ----------------
__global__ void k_h_l0(const float* __restrict__ x, const float* __restrict__ W, int n) {
    int tid = blockIdx.x * blockDim.x + threadIdx.x;
    if (tid >= n * 512) return;
    int v = tid >> 9, j = tid & 511;
    g_h[tid] = x[2 * v] * W[2 * j] + x[2 * v + 1] * W[2 * j + 1];
}

// NEW: tiled GEMM for layer 1: g_h[v][jb*128+j] = sum_k g_xa[v][k] * W[(jb*128+j)][k]
// grid (n/32, 4), block 256, smem 86016 B
#define GEMM_SMEM ((128 * 132 + 128 * 36) * 4)
__global__ void k_gemm1(const float* __restrict__ W, int n) {
    extern __shared__ float sm[];
    float* w_s = sm;               // w_s[k*132 + j]
    float* x_s = sm + 128 * 132;   // x_s[k*36 + nl]
    int tid = threadIdx.x;
    int node0 = blockIdx.x * 32;
    int jb = blockIdx.y;

    for (int idx = tid; idx < 32 * 128; idx += 256) {
        int nl = idx >> 7, k = idx & 127;
        int nd = node0 + nl;
        x_s[k * 36 + nl] = (nd < n) ? g_xa[(size_t)nd * 128 + k] : 0.f;
    }
    for (int idx = tid; idx < 128 * 128; idx += 256) {
        int j = idx >> 7, k = idx & 127;
        w_s[k * 132 + j] = W[(size_t)(jb * 128 + j) * 128 + k];
    }
    __syncthreads();

    int jt = (tid & 31) * 4;
    int nt = (tid >> 5) * 4;
    float acc[4][4];
#pragma unroll
    for (int r = 0; r < 4; r++)
#pragma unroll
        for (int c = 0; c < 4; c++) acc[r][c] = 0.f;

#pragma unroll 8
    for (int k = 0; k < 128; k++) {
        float4 xv = *(const float4*)&x_s[k * 36 + nt];
        float4 wv = *(const float4*)&w_s[k * 132 + jt];
        acc[0][0] = __fmaf_rn(xv.x, wv.x, acc[0][0]); acc[0][1] = __fmaf_rn(xv.x, wv.y, acc[0][1]);
        acc[0][2] = __fmaf_rn(xv.x, wv.z, acc[0][2]); acc[0][3] = __fmaf_rn(xv.x, wv.w, acc[0][3]);
        acc[1][0] = __fmaf_rn(xv.y, wv.x, acc[1][0]); acc[1][1] = __fmaf_rn(xv.y, wv.y, acc[1][1]);
        acc[1][2] = __fmaf_rn(xv.y, wv.z, acc[1][2]); acc[1][3] = __fmaf_rn(xv.y, wv.w, acc[1][3]);
        acc[2][0] = __fmaf_rn(xv.z, wv.x, acc[2][0]); acc[2][1] = __fmaf_rn(xv.z, wv.y, acc[2][1]);
        acc[2][2] = __fmaf_rn(xv.z, wv.z, acc[2][2]); acc[2][3] = __fmaf_rn(xv.z, wv.w, acc[2][3]);
        acc[3][0] = __fmaf_rn(xv.w, wv.x, acc[3][0]); acc[3][1] = __fmaf_rn(xv.w, wv.y, acc[3][1]);
        acc[3][2] = __fmaf_rn(xv.w, wv.z, acc[3][2]); acc[3][3] = __fmaf_rn(xv.w, wv.w, acc[3][3]);
    }

#pragma unroll
    for (int r = 0; r < 4; r++) {
        int nd = node0 + nt + r;
        if (nd < n) {
            *(float4*)&g_h[(size_t)nd * 512 + jb * 128 + jt] =
                make_float4(acc[r][0], acc[r][1], acc[r][2], acc[r][3]);
        }
    }
}

__global__ void k_h_l2(const float* __restrict__ W, int n) {
    int tid = blockIdx.x * blockDim.x + threadIdx.x;
    if (tid >= n * 3) return;
    int v = tid / 3, o = tid - v * 3;
    const float* xr = &g_xb[(size_t)v * 128];
    const float* wr = &W[(size_t)o * 128];
    float acc = 0.f;
    for (int k = 0; k < 128; k++) acc = __fmaf_rn(xr[k], wr[k], acc);
    g_h2[tid] = acc;
}

// ---------------- NEW: warp-per-node coalesced score kernel ----------------
__global__ void k_scoreW(const float* __restrict__ as_, const float* __restrict__ ad_, int n) {
    int v = (blockIdx.x * blockDim.x + threadIdx.x) >> 5;
    int lane = threadIdx.x & 31;
    if (v >= n) return;
    float sp[4], dp[4];
#pragma unroll
    for (int hd = 0; hd < 4; hd++) {
        float4 hv = *(const float4*)&g_h[(size_t)v * 512 + hd * 128 + lane * 4];
        float4 av = *(const float4*)&as_[hd * 128 + lane * 4];
        float4 dv = *(const float4*)&ad_[hd * 128 + lane * 4];
        float s = hv.x * av.x + hv.y * av.y + hv.z * av.z + hv.w * av.w;
        float d = hv.x * dv.x + hv.y * dv.y + hv.z * dv.z + hv.w * dv.w;
#pragma unroll
        for (int o = 16; o > 0; o >>= 1) {
            s += __shfl_xor_sync(FULL, s, o);
            d += __shfl_xor_sync(FULL, d, o);
        }
        sp[hd] = s;
        dp[hd] = d;
    }
    if (lane == 0) {
#pragma unroll
        for (int hd = 0; hd < 4; hd++) {
            g_s[v * 4 + hd] = sp[hd];
            g_d[v * 4 + hd] = dp[hd];
        }
    }
}

__global__ void k_score2(const float* __restrict__ as_, const float* __restrict__ ad_, int n) {
    int v = blockIdx.x * blockDim.x + threadIdx.x;
    if (v >= n) return;
    float s = 0.f, d = 0.f;
    for (int o = 0; o < 3; o++) {
        s = __fmaf_rn(g_h2[v * 3 + o], as_[o], s);
        d = __fmaf_rn(g_h2[v * 3 + o], ad_[o], d);
    }
    g_s[v] = s;
    g_d[v] = d;
}

// ---------------- segment max ----------------
__global__ void k_maxk(int m) {
    int tid = blockIdx.x * blockDim.x + threadIdx.x;
    if (tid >= m * 4) return;
    int i = tid >> 2, hd = tid & 3;
    int src = g_esrc[i], dst = g_edst[i];
    float l = lrelu(g_s[src * 4 + hd] + g_d[dst * 4 + hd]);
    atomicMax(&g_m[dst * 4 + hd], fkey(l));
}
__global__ void k_max2(int m) {
    int i = blockIdx.x * blockDim.x + threadIdx.x;
    if (i >= m) return;
    float l = lrelu(g_s[g_esrc[i]] + g_d[g_edst[i]]);
    atomicMax(&g_m[g_edst[i]], fkey(l));
}

// ---------------- exp + segment sum ----------------
__global__ void k_expsum(int m) {
    int tid = blockIdx.x * blockDim.x + threadIdx.x;
    if (tid >= m * 4) return;
    int i = tid >> 2, hd = tid & 3;
    int src = g_esrc[i], dst = g_edst[i];
    float l = lrelu(g_s[src * 4 + hd] + g_d[dst * 4 + hd]);
    float p = exp_acc(l - funkey(g_m[dst * 4 + hd]));
    g_p[i * 4 + hd] = p;
    atomicAdd(&g_sum[dst * 4 + hd], p);
}
__global__ void k_expsum2(int m) {
    int i = blockIdx.x * blockDim.x + threadIdx.x;
    if (i >= m) return;
    int dst = g_edst[i];
    float l = lrelu(g_s[g_esrc[i]] + g_d[dst]);
    float p = exp_acc(l - funkey(g_m[dst]));
    g_p[i] = p;
    atomicAdd(&g_sum[dst], p);
}

// ---------------- warp-per-node CSR gather + finalize (layers 0/1) ----------------
__global__ void k_gath(const float* __restrict__ bias,
                       const float* __restrict__ bng, const float* __restrict__ bnb,
                       const float* __restrict__ bnm, const float* __restrict__ bnv,
                       int outsel, int n) {
    int v = (blockIdx.x * blockDim.x + threadIdx.x) >> 5;
    int lane = threadIdx.x & 31;
    if (v >= n) return;
    int beg = g_rowptr[v], end = g_rowptr[v + 1];

    float acc[16];
#pragma unroll
    for (int i = 0; i < 16; i++) acc[i] = 0.f;

    for (int base = beg; base < end; base += 32) {
        int idx = base + lane;
        int sv = 0;
        float4 pv = make_float4(0.f, 0.f, 0.f, 0.f);
        if (idx < end) {
            int eid = g_csr[idx];
            sv = g_esrc[eid];
            pv = *(const float4*)&g_p[(size_t)eid * 4];
        }
        int cnt = min(32, end - base);
        for (int t = 0; t < cnt; t++) {
            int s = __shfl_sync(FULL, sv, t);
            float p0 = __shfl_sync(FULL, pv.x, t);
            float p1 = __shfl_sync(FULL, pv.y, t);
            float p2 = __shfl_sync(FULL, pv.z, t);
            float p3 = __shfl_sync(FULL, pv.w, t);
            const float4* hp = (const float4*)(g_h + (size_t)s * 512);
            float4 h0 = hp[lane];
            float4 h1 = hp[32 + lane];
            float4 h2 = hp[64 + lane];
            float4 h3 = hp[96 + lane];
            acc[0]  += h0.x * p0; acc[1]  += h0.y * p0; acc[2]  += h0.z * p0; acc[3]  += h0.w * p0;
            acc[4]  += h1.x * p1; acc[5]  += h1.y * p1; acc[6]  += h1.z * p1; acc[7]  += h1.w * p1;
            acc[8]  += h2.x * p2; acc[9]  += h2.y * p2; acc[10] += h2.z * p2; acc[11] += h2.w * p2;
            acc[12] += h3.x * p3; acc[13] += h3.y * p3; acc[14] += h3.z * p3; acc[15] += h3.w * p3;
        }
    }

    float d0 = __fadd_rn(g_sum[v * 4 + 0], 1e-16f);
    float d1 = __fadd_rn(g_sum[v * 4 + 1], 1e-16f);
    float d2 = __fadd_rn(g_sum[v * 4 + 2], 1e-16f);
    float d3 = __fadd_rn(g_sum[v * 4 + 3], 1e-16f);

    int c = lane * 4;
    float vals[4];
#pragma unroll
    for (int j = 0; j < 4; j++) {
        float a = 0.f;
        a = __fadd_rn(a, __fdiv_rn(acc[j],      d0));
        a = __fadd_rn(a, __fdiv_rn(acc[4 + j],  d1));
        a = __fadd_rn(a, __fdiv_rn(acc[8 + j],  d2));
        a = __fadd_rn(a, __fdiv_rn(acc[12 + j], d3));
        float val = __fmul_rn(a, 0.25f);
        val = __fadd_rn(val, bias[c + j]);
        val = elu_acc(val);
        float inv = __frsqrt_rn(__fadd_rn(bnv[c + j], 1e-5f));
        val = __fadd_rn(__fmul_rn(__fmul_rn(__fsub_rn(val, bnm[c + j]), inv), bng[c + j]), bnb[c + j]);
        vals[j] = val;
    }
    float* xout = outsel ? g_xb : g_xa;
    *(float4*)&xout[(size_t)v * 128 + c] = make_float4(vals[0], vals[1], vals[2], vals[3]);
}

// ---------------- layer-2 scatter (tiny) ----------------
__global__ void k_scat2(int m) {
    int i = blockIdx.x * blockDim.x + threadIdx.x;
    if (i >= m) return;
    int src = g_esrc[i], dst = g_edst[i];
    float p = g_p[i];
#pragma unroll
    for (int o = 0; o < 3; o++)
        atomicAdd(&g_out2[dst * 3 + o], p * g_h2[src * 3 + o]);
}

// ---------------- layer-2 finalize + ODE epilogue ----------------
__global__ void k_epi(const float* __restrict__ b2,
                      const float* __restrict__ kk, const float* __restrict__ dd,
                      const float* __restrict__ t00, const float* __restrict__ u00,
                      const float* __restrict__ t, float* __restrict__ out, int n) {
    int v = blockIdx.x * blockDim.x + threadIdx.x;
    if (v >= n) return;
    float denom = __fadd_rn(g_sum[v], 1e-16f);
    float ar  = elu_acc(__fadd_rn(__fdiv_rn(g_out2[v * 3 + 0], denom), b2[0]));
    float gam = elu_acc(__fadd_rn(__fdiv_rn(g_out2[v * 3 + 1], denom), b2[1]));
    float bet = elu_acc(__fadd_rn(__fdiv_rn(g_out2[v * 3 + 2], denom), b2[2]));

    float tt = t[v];
    float K = kk[0], D = dd[0], T0 = t00[0], U0 = u00[0];

    float z = __fmul_rn(K, __fsub_rn(__fsub_rn(tt, T0), D));
    float S = __fdiv_rn(1.0f, __fadd_rn(1.0f, exp_acc(-z)));
    float oneMS = __fsub_rn(1.0f, S);

    float eb  = exp_acc(__fmul_rn(-bet, tt));
    float eg  = exp_acc(__fmul_rn(-gam, tt));
    float tmt0 = __fsub_rn(tt, T0);
    float ebs = exp_acc(__fmul_rn(-bet, tmt0));
    float egs = exp_acc(__fmul_rn(-gam, tmt0));
    float ab = __fdiv_rn(ar, bet);
    float ag = __fdiv_rn(ar, gam);

    float tu = __fadd_rn(
                 __fadd_rn(__fmul_rn(__fmul_rn(ab, __fsub_rn(1.0f, eb)), oneMS),
                           __fmul_rn(ab, S)),
                 __fmul_rn(__fsub_rn(__fmul_rn(U0, ebs), ab), S));

    float gmb = __fsub_rn(gam, bet);
    float term1 = __fadd_rn(__fmul_rn(ag, __fsub_rn(1.0f, eg)),
                            __fmul_rn(__fdiv_rn(ar, gmb), __fsub_rn(eg, eb)));
    float term3 = __fmul_rn(__fmul_rn(__fdiv_rn(__fmul_rn(bet, U0), gmb),
                                      __fsub_rn(egs, ebs)), S);
    float ts = __fadd_rn(__fadd_rn(__fmul_rn(term1, oneMS), __fmul_rn(ag, S)), term3);

    out[v] = tu;
    out[n + v] = ts;
}

// ---------------- launch ----------------
extern "C" void kernel_launch(void* const* d_in, const int* in_sizes, int n_in,
                              void* d_out, int out_size) {
    int off = (n_in >= 28) ? 0 : -1;
    const float* x    = (const float*)d_in[0];
    const int*   ei   = (const int*)d_in[1];
    const float* W0   = (const float*)d_in[3 + off];
    const float* as0  = (const float*)d_in[4 + off];
    const float* ad0  = (const float*)d_in[5 + off];
    const float* b0   = (const float*)d_in[6 + off];
    const float* W1   = (const float*)d_in[7 + off];
    const float* as1  = (const float*)d_in[8 + off];
    const float* ad1  = (const float*)d_in[9 + off];
    const float* b1   = (const float*)d_in[10 + off];
    const float* W2   = (const float*)d_in[11 + off];
    const float* as2  = (const float*)d_in[12 + off];
    const float* ad2  = (const float*)d_in[13 + off];
    const float* b2   = (const float*)d_in[14 + off];
    const float* bng0 = (const float*)d_in[15 + off];
    const float* bnb0 = (const float*)d_in[16 + off];
    const float* bnm0 = (const float*)d_in[17 + off];
    const float* bnv0 = (const float*)d_in[18 + off];
    const float* bng1 = (const float*)d_in[19 + off];
    const float* bnb1 = (const float*)d_in[20 + off];
    const float* bnm1 = (const float*)d_in[21 + off];
    const float* bnv1 = (const float*)d_in[22 + off];
    const float* kk   = (const float*)d_in[23 + off];
    const float* dd   = (const float*)d_in[24 + off];
    const float* t00  = (const float*)d_in[25 + off];
    const float* u00  = (const float*)d_in[26 + off];
    const float* t    = (const float*)d_in[27 + off];
    float* out = (float*)d_out;

    int n = in_sizes[0] / 2;
    int e = in_sizes[1] / 2;
    int m = e + n;

    const int B = 256;
    auto nb = [](long long x, int b) { return (int)((x + b - 1) / b); };
    int nwb = nb((long long)n * 32, B);   // warp-per-node grids

    cudaFuncSetAttribute(k_gemm1, cudaFuncAttributeMaxDynamicSharedMemorySize, GEMM_SMEM);

    k_edges<<<nb(m, B), B>>>(ei, e, m);

    // CSR (dst-indexed, edge ids)
    k_zero<<<nb(n, B), B>>>(n);
    k_count<<<nb(m, B), B>>>(m);
    k_scan<<<1, 512>>>(n, m);
    k_fill<<<nb(m, B), B>>>(m);

    // ---- layer 0 ----
    k_clearS<<<nb(n * 4, B), B>>>(n);
    k_h_l0<<<nb((long long)n * 512, B), B>>>(x, W0, n);
    k_scoreW<<<nwb, B>>>(as0, ad0, n);
    k_maxk<<<nb((long long)m * 4, B), B>>>(m);
    k_expsum<<<nb((long long)m * 4, B), B>>>(m);
    k_gath<<<nwb, B>>>(b0, bng0, bnb0, bnm0, bnv0, 0, n);

    // ---- layer 1 ----
    k_clearS<<<nb(n * 4, B), B>>>(n);
    {
        dim3 grid(nb(n, 32), 4);
        k_gemm1<<<grid, 256, GEMM_SMEM>>>(W1, n);
    }
    k_scoreW<<<nwb, B>>>(as1, ad1, n);
    k_maxk<<<nb((long long)m * 4, B), B>>>(m);
    k_expsum<<<nb((long long)m * 4, B), B>>>(m);
    k_gath<<<nwb, B>>>(b1, bng1, bnb1, bnm1, bnv1, 1, n);

    // ---- layer 2 + epilogue ----
    k_clear2<<<nb((long long)n * 3, B), B>>>(n);
    k_h_l2<<<nb((long long)n * 3, B), B>>>(W2, n);
    k_score2<<<nb(n, B), B>>>(as2, ad2, n);
    k_max2<<<nb(m, B), B>>>(m);
    k_expsum2<<<nb(m, B), B>>>(m);
    k_scat2<<<nb(m, B), B>>>(m);
    k_epi<<<nb(n, B), B>>>(b2, kk, dd, t00, u00, t, out, n);
}

// round 7
// speedup vs baseline: 14.9624x; 1.1614x over previous
#include <cuda_runtime.h>
#include <math.h>

#define NN 20000
#define EE 320000
#define MMX (EE + NN)
#define FULL 0xffffffffu

// ---------------- scratch ----------------
__device__ float g_h[NN * 512];
__device__ float g_xa[NN * 128];
__device__ float g_xb[NN * 128];
__device__ float g_s[NN * 4];            // src scores (per head)
__device__ float g_d[NN * 4];            // dst scores (per head)
__device__ float g_sum[NN * 4];          // segment exp-sum
__device__ float g_pc[MMX * 4];          // per-edge exp values, CSR order
__device__ int g_esrc[MMX];
__device__ int g_edst[MMX];
__device__ float g_h2[NN * 3];
__device__ int g_deg[NN];
__device__ int g_rowptr[NN + 1];
__device__ int g_cursor[NN];
__device__ int g_csrs[MMX];              // CSR by dst: src node per slot

// ---------------- accurate exp/expm1/elu ----------------
__device__ __forceinline__ float exp_acc(float x) {
    x = fminf(fmaxf(x, -87.0f), 87.0f);
    float kf = rintf(__fmul_rn(x, 1.4426950408889634f));
    float r = __fmaf_rn(kf, -0.69314718246459960938f, x);
    r = __fmaf_rn(kf, 1.9046542743622637e-9f, r);
    float p = 1.9841269841269841e-4f;
    p = __fmaf_rn(p, r, 1.3888888888888889e-3f);
    p = __fmaf_rn(p, r, 8.3333333333333332e-3f);
    p = __fmaf_rn(p, r, 4.1666666666666664e-2f);
    p = __fmaf_rn(p, r, 1.6666666666666666e-1f);
    p = __fmaf_rn(p, r, 0.5f);
    p = __fmaf_rn(p, r, 1.0f);
    p = __fmaf_rn(p, r, 1.0f);
    int ik = (int)kf;
    float s = __int_as_float((ik + 127) << 23);
    return __fmul_rn(p, s);
}
__device__ __forceinline__ float expm1_acc(float x) {
    if (x < -0.34657359f) return __fadd_rn(exp_acc(x), -1.0f);
    float p = 1.9841269841269841e-4f;
    p = __fmaf_rn(p, x, 1.3888888888888889e-3f);
    p = __fmaf_rn(p, x, 8.3333333333333332e-3f);
    p = __fmaf_rn(p, x, 4.1666666666666664e-2f);
    p = __fmaf_rn(p, x, 1.6666666666666666e-1f);
    p = __fmaf_rn(p, x, 0.5f);
    p = __fmaf_rn(p, x, 1.0f);
    return __fmul_rn(p, x);
}
__device__ __forceinline__ float elu_acc(float x) {
    return x > 0.f ? x : expm1_acc(x);
}
__device__ __forceinline__ float lrelu(float x) {
    return x >= 0.f ? x : 0.2f * x;
}

// ---------------- edges + degree count (fused) ----------------
__global__ void k_zero(int n) {
    int i = blockIdx.x * blockDim.x + threadIdx.x;
    if (i < n) g_deg[i] = 0;
}
__global__ void k_edges_count(const int* __restrict__ ei, int e, int m) {
    int i = blockIdx.x * blockDim.x + threadIdx.x;
    if (i >= m) return;
    int s, d;
    if (i < e) { s = ei[i]; d = ei[e + i]; }
    else       { s = i - e; d = i - e; }
    g_esrc[i] = s;
    g_edst[i] = d;
    atomicAdd(&g_deg[d], 1);
}

// ---------------- fast single-block scan (1024 threads, warp shuffles) ----------------
__global__ void k_scan(int n, int m) {
    __shared__ int wsum[32];
    int t = threadIdx.x;                 // 0..1023
    int lane = t & 31, wid = t >> 5;
    int chunk = (n + 1023) / 1024;
    int b0 = t * chunk;
    int b1 = min(b0 + chunk, n);
    int s = 0;
    for (int i = b0; i < b1; i++) s += g_deg[i];
    int v = s;
#pragma unroll
    for (int o = 1; o < 32; o <<= 1) {
        int u = __shfl_up_sync(FULL, v, o);
        if (lane >= o) v += u;
    }
    if (lane == 31) wsum[wid] = v;
    __syncthreads();
    if (wid == 0) {
        int w = wsum[lane];
#pragma unroll
        for (int o = 1; o < 32; o <<= 1) {
            int u = __shfl_up_sync(FULL, w, o);
            if (lane >= o) w += u;
        }
        wsum[lane] = w;
    }
    __syncthreads();
    int run = (v - s) + (wid > 0 ? wsum[wid - 1] : 0);
    for (int i = b0; i < b1; i++) {
        g_rowptr[i] = run;
        g_cursor[i] = run;
        run += g_deg[i];
    }
    if (t == 0) g_rowptr[n] = m;
}
__global__ void k_fill(int m) {
    int i = blockIdx.x * blockDim.x + threadIdx.x;
    if (i < m) {
        int pos = atomicAdd(&g_cursor[g_edst[i]], 1);
        g_csrs[pos] = g_esrc[i];
    }
}

// ---------------- layer 0 h ----------------
__global__ void k_h_l0(const float* __restrict__ x, const float* __restrict__ W, int n) {
    int tid = blockIdx.x * blockDim.x + threadIdx.x;
    if (tid >= n * 512) return;
    int v = tid >> 9, j = tid & 511;
    g_h[tid] = x[2 * v] * W[2 * j] + x[2 * v + 1] * W[2 * j + 1];
}

// ---------------- layer 1 tiled GEMM ----------------
#define GEMM_SMEM ((128 * 132 + 128 * 36) * 4)
__global__ void k_gemm1(const float* __restrict__ W, int n) {
    extern __shared__ float sm[];
    float* w_s = sm;               // w_s[k*132 + j]
    float* x_s = sm + 128 * 132;   // x_s[k*36 + nl]
    int tid = threadIdx.x;
    int node0 = blockIdx.x * 32;
    int jb = blockIdx.y;

    for (int idx = tid; idx < 32 * 128; idx += 256) {
        int nl = idx >> 7, k = idx & 127;
        int nd = node0 + nl;
        x_s[k * 36 + nl] = (nd < n) ? g_xa[(size_t)nd * 128 + k] : 0.f;
    }
    for (int idx = tid; idx < 128 * 128; idx += 256) {
        int j = idx >> 7, k = idx & 127;
        w_s[k * 132 + j] = W[(size_t)(jb * 128 + j) * 128 + k];
    }
    __syncthreads();

    int jt = (tid & 31) * 4;
    int nt = (tid >> 5) * 4;
    float acc[4][4];
#pragma unroll
    for (int r = 0; r < 4; r++)
#pragma unroll
        for (int c = 0; c < 4; c++) acc[r][c] = 0.f;

#pragma unroll 8
    for (int k = 0; k < 128; k++) {
        float4 xv = *(const float4*)&x_s[k * 36 + nt];
        float4 wv = *(const float4*)&w_s[k * 132 + jt];
        acc[0][0] = __fmaf_rn(xv.x, wv.x, acc[0][0]); acc[0][1] = __fmaf_rn(xv.x, wv.y, acc[0][1]);
        acc[0][2] = __fmaf_rn(xv.x, wv.z, acc[0][2]); acc[0][3] = __fmaf_rn(xv.x, wv.w, acc[0][3]);
        acc[1][0] = __fmaf_rn(xv.y, wv.x, acc[1][0]); acc[1][1] = __fmaf_rn(xv.y, wv.y, acc[1][1]);
        acc[1][2] = __fmaf_rn(xv.y, wv.z, acc[1][2]); acc[1][3] = __fmaf_rn(xv.y, wv.w, acc[1][3]);
        acc[2][0] = __fmaf_rn(xv.z, wv.x, acc[2][0]); acc[2][1] = __fmaf_rn(xv.z, wv.y, acc[2][1]);
        acc[2][2] = __fmaf_rn(xv.z, wv.z, acc[2][2]); acc[2][3] = __fmaf_rn(xv.z, wv.w, acc[2][3]);
        acc[3][0] = __fmaf_rn(xv.w, wv.x, acc[3][0]); acc[3][1] = __fmaf_rn(xv.w, wv.y, acc[3][1]);
        acc[3][2] = __fmaf_rn(xv.w, wv.z, acc[3][2]); acc[3][3] = __fmaf_rn(xv.w, wv.w, acc[3][3]);
    }

#pragma unroll
    for (int r = 0; r < 4; r++) {
        int nd = node0 + nt + r;
        if (nd < n) {
            *(float4*)&g_h[(size_t)nd * 512 + jb * 128 + jt] =
                make_float4(acc[r][0], acc[r][1], acc[r][2], acc[r][3]);
        }
    }
}

// ---------------- warp-per-node coalesced score kernel (layers 0/1) ----------------
__global__ void k_scoreW(const float* __restrict__ as_, const float* __restrict__ ad_, int n) {
    int v = (blockIdx.x * blockDim.x + threadIdx.x) >> 5;
    int lane = threadIdx.x & 31;
    if (v >= n) return;
    float sp[4], dp[4];
#pragma unroll
    for (int hd = 0; hd < 4; hd++) {
        float4 hv = *(const float4*)&g_h[(size_t)v * 512 + hd * 128 + lane * 4];
        float4 av = *(const float4*)&as_[hd * 128 + lane * 4];
        float4 dv = *(const float4*)&ad_[hd * 128 + lane * 4];
        float s = hv.x * av.x + hv.y * av.y + hv.z * av.z + hv.w * av.w;
        float d = hv.x * dv.x + hv.y * dv.y + hv.z * dv.z + hv.w * dv.w;
#pragma unroll
        for (int o = 16; o > 0; o >>= 1) {
            s += __shfl_xor_sync(FULL, s, o);
            d += __shfl_xor_sync(FULL, d, o);
        }
        sp[hd] = s;
        dp[hd] = d;
    }
    if (lane == 0) {
        *(float4*)&g_s[v * 4] = make_float4(sp[0], sp[1], sp[2], sp[3]);
        *(float4*)&g_d[v * 4] = make_float4(dp[0], dp[1], dp[2], dp[3]);
    }
}

// ---------------- warp-per-node softmax over CSR (layers 0/1): max, exp, sum ----------------
__global__ void k_smax(int n) {
    int v = (blockIdx.x * blockDim.x + threadIdx.x) >> 5;
    int lane = threadIdx.x & 31;
    if (v >= n) return;
    int beg = g_rowptr[v], end = g_rowptr[v + 1];
    float4 dv = *(const float4*)&g_d[v * 4];

    float m0 = -1e30f, m1 = -1e30f, m2 = -1e30f, m3 = -1e30f;
    for (int idx = beg + lane; idx < end; idx += 32) {
        int s = g_csrs[idx];
        float4 sv = *(const float4*)&g_s[s * 4];
        m0 = fmaxf(m0, lrelu(sv.x + dv.x));
        m1 = fmaxf(m1, lrelu(sv.y + dv.y));
        m2 = fmaxf(m2, lrelu(sv.z + dv.z));
        m3 = fmaxf(m3, lrelu(sv.w + dv.w));
    }
#pragma unroll
    for (int o = 16; o > 0; o >>= 1) {
        m0 = fmaxf(m0, __shfl_xor_sync(FULL, m0, o));
        m1 = fmaxf(m1, __shfl_xor_sync(FULL, m1, o));
        m2 = fmaxf(m2, __shfl_xor_sync(FULL, m2, o));
        m3 = fmaxf(m3, __shfl_xor_sync(FULL, m3, o));
    }

    float s0 = 0.f, s1 = 0.f, s2 = 0.f, s3 = 0.f;
    for (int idx = beg + lane; idx < end; idx += 32) {
        int s = g_csrs[idx];
        float4 sv = *(const float4*)&g_s[s * 4];
        float p0 = exp_acc(lrelu(sv.x + dv.x) - m0);
        float p1 = exp_acc(lrelu(sv.y + dv.y) - m1);
        float p2 = exp_acc(lrelu(sv.z + dv.z) - m2);
        float p3 = exp_acc(lrelu(sv.w + dv.w) - m3);
        s0 += p0; s1 += p1; s2 += p2; s3 += p3;
        *(float4*)&g_pc[(size_t)idx * 4] = make_float4(p0, p1, p2, p3);
    }
#pragma unroll
    for (int o = 16; o > 0; o >>= 1) {
        s0 += __shfl_xor_sync(FULL, s0, o);
        s1 += __shfl_xor_sync(FULL, s1, o);
        s2 += __shfl_xor_sync(FULL, s2, o);
        s3 += __shfl_xor_sync(FULL, s3, o);
    }
    if (lane == 0)
        *(float4*)&g_sum[v * 4] = make_float4(s0, s1, s2, s3);
}

// ---------------- warp-per-node CSR gather + finalize (layers 0/1) ----------------
__global__ void k_gath(const float* __restrict__ bias,
                       const float* __restrict__ bng, const float* __restrict__ bnb,
                       const float* __restrict__ bnm, const float* __restrict__ bnv,
                       int outsel, int n) {
    int v = (blockIdx.x * blockDim.x + threadIdx.x) >> 5;
    int lane = threadIdx.x & 31;
    if (v >= n) return;
    int beg = g_rowptr[v], end = g_rowptr[v + 1];

    float acc[16];
#pragma unroll
    for (int i = 0; i < 16; i++) acc[i] = 0.f;

    for (int base = beg; base < end; base += 32) {
        int idx = base + lane;
        int sv = 0;
        float4 pv = make_float4(0.f, 0.f, 0.f, 0.f);
        if (idx < end) {
            sv = g_csrs[idx];
            pv = *(const float4*)&g_pc[(size_t)idx * 4];
        }
        int cnt = min(32, end - base);
        for (int t = 0; t < cnt; t++) {
            int s = __shfl_sync(FULL, sv, t);
            float p0 = __shfl_sync(FULL, pv.x, t);
            float p1 = __shfl_sync(FULL, pv.y, t);
            float p2 = __shfl_sync(FULL, pv.z, t);
            float p3 = __shfl_sync(FULL, pv.w, t);
            const float4* hp = (const float4*)(g_h + (size_t)s * 512);
            float4 h0 = hp[lane];
            float4 h1 = hp[32 + lane];
            float4 h2 = hp[64 + lane];
            float4 h3 = hp[96 + lane];
            acc[0]  += h0.x * p0; acc[1]  += h0.y * p0; acc[2]  += h0.z * p0; acc[3]  += h0.w * p0;
            acc[4]  += h1.x * p1; acc[5]  += h1.y * p1; acc[6]  += h1.z * p1; acc[7]  += h1.w * p1;
            acc[8]  += h2.x * p2; acc[9]  += h2.y * p2; acc[10] += h2.z * p2; acc[11] += h2.w * p2;
            acc[12] += h3.x * p3; acc[13] += h3.y * p3; acc[14] += h3.z * p3; acc[15] += h3.w * p3;
        }
    }

    float4 sv4 = *(const float4*)&g_sum[v * 4];
    float d0 = __fadd_rn(sv4.x, 1e-16f);
    float d1 = __fadd_rn(sv4.y, 1e-16f);
    float d2 = __fadd_rn(sv4.z, 1e-16f);
    float d3 = __fadd_rn(sv4.w, 1e-16f);

    int c = lane * 4;
    float vals[4];
#pragma unroll
    for (int j = 0; j < 4; j++) {
        float a = 0.f;
        a = __fadd_rn(a, __fdiv_rn(acc[j],      d0));
        a = __fadd_rn(a, __fdiv_rn(acc[4 + j],  d1));
        a = __fadd_rn(a, __fdiv_rn(acc[8 + j],  d2));
        a = __fadd_rn(a, __fdiv_rn(acc[12 + j], d3));
        float val = __fmul_rn(a, 0.25f);
        val = __fadd_rn(val, bias[c + j]);
        val = elu_acc(val);
        float inv = __frsqrt_rn(__fadd_rn(bnv[c + j], 1e-5f));
        val = __fadd_rn(__fmul_rn(__fmul_rn(__fsub_rn(val, bnm[c + j]), inv), bng[c + j]), bnb[c + j]);
        vals[j] = val;
    }
    float* xout = outsel ? g_xb : g_xa;
    *(float4*)&xout[(size_t)v * 128 + c] = make_float4(vals[0], vals[1], vals[2], vals[3]);
}

// ---------------- layer 2: fused h2 + scores (warp per node, coalesced) ----------------
__global__ void k_l2(const float* __restrict__ W, const float* __restrict__ as_,
                     const float* __restrict__ ad_, int n) {
    int v = (blockIdx.x * blockDim.x + threadIdx.x) >> 5;
    int lane = threadIdx.x & 31;
    if (v >= n) return;
    float4 xv = *(const float4*)&g_xb[(size_t)v * 128 + lane * 4];
    float p[3];
#pragma unroll
    for (int o = 0; o < 3; o++) {
        float4 wv = *(const float4*)&W[o * 128 + lane * 4];
        float pp = __fmaf_rn(xv.x, wv.x, __fmaf_rn(xv.y, wv.y, __fmaf_rn(xv.z, wv.z, xv.w * wv.w)));
#pragma unroll
        for (int off = 16; off > 0; off >>= 1) pp += __shfl_xor_sync(FULL, pp, off);
        p[o] = pp;
    }
    if (lane == 0) {
        g_h2[v * 3 + 0] = p[0];
        g_h2[v * 3 + 1] = p[1];
        g_h2[v * 3 + 2] = p[2];
        g_s[v] = __fmaf_rn(p[0], as_[0], __fmaf_rn(p[1], as_[1], p[2] * as_[2]));
        g_d[v] = __fmaf_rn(p[0], ad_[0], __fmaf_rn(p[1], ad_[1], p[2] * ad_[2]));
    }
}

// ---------------- layer 2: warp-per-node softmax + aggregate + ODE epilogue ----------------
__global__ void k_smax2epi(const float* __restrict__ b2,
                           const float* __restrict__ kk, const float* __restrict__ dd,
                           const float* __restrict__ t00, const float* __restrict__ u00,
                           const float* __restrict__ t, float* __restrict__ out, int n) {
    int v = (blockIdx.x * blockDim.x + threadIdx.x) >> 5;
    int lane = threadIdx.x & 31;
    if (v >= n) return;
    int beg = g_rowptr[v], end = g_rowptr[v + 1];
    float sd = g_d[v];

    float mx = -1e30f;
    for (int idx = beg + lane; idx < end; idx += 32)
        mx = fmaxf(mx, lrelu(g_s[g_csrs[idx]] + sd));
#pragma unroll
    for (int o = 16; o > 0; o >>= 1) mx = fmaxf(mx, __shfl_xor_sync(FULL, mx, o));

    float sum = 0.f, a0 = 0.f, a1 = 0.f, a2 = 0.f;
    for (int idx = beg + lane; idx < end; idx += 32) {
        int s = g_csrs[idx];
        float p = exp_acc(lrelu(g_s[s] + sd) - mx);
        sum += p;
        a0 = __fmaf_rn(p, g_h2[s * 3 + 0], a0);
        a1 = __fmaf_rn(p, g_h2[s * 3 + 1], a1);
        a2 = __fmaf_rn(p, g_h2[s * 3 + 2], a2);
    }
#pragma unroll
    for (int o = 16; o > 0; o >>= 1) {
        sum += __shfl_xor_sync(FULL, sum, o);
        a0 += __shfl_xor_sync(FULL, a0, o);
        a1 += __shfl_xor_sync(FULL, a1, o);
        a2 += __shfl_xor_sync(FULL, a2, o);
    }
    if (lane == 0) {
        float denom = __fadd_rn(sum, 1e-16f);
        float ar  = elu_acc(__fadd_rn(__fdiv_rn(a0, denom), b2[0]));
        float gam = elu_acc(__fadd_rn(__fdiv_rn(a1, denom), b2[1]));
        float bet = elu_acc(__fadd_rn(__fdiv_rn(a2, denom), b2[2]));

        float tt = t[v];
        float K = kk[0], D = dd[0], T0 = t00[0], U0 = u00[0];

        float z = __fmul_rn(K, __fsub_rn(__fsub_rn(tt, T0), D));
        float S = __fdiv_rn(1.0f, __fadd_rn(1.0f, exp_acc(-z)));
        float oneMS = __fsub_rn(1.0f, S);

        float eb  = exp_acc(__fmul_rn(-bet, tt));
        float eg  = exp_acc(__fmul_rn(-gam, tt));
        float tmt0 = __fsub_rn(tt, T0);
        float ebs = exp_acc(__fmul_rn(-bet, tmt0));
        float egs = exp_acc(__fmul_rn(-gam, tmt0));
        float ab = __fdiv_rn(ar, bet);
        float ag = __fdiv_rn(ar, gam);

        float tu = __fadd_rn(
                     __fadd_rn(__fmul_rn(__fmul_rn(ab, __fsub_rn(1.0f, eb)), oneMS),
                               __fmul_rn(ab, S)),
                     __fmul_rn(__fsub_rn(__fmul_rn(U0, ebs), ab), S));

        float gmb = __fsub_rn(gam, bet);
        float term1 = __fadd_rn(__fmul_rn(ag, __fsub_rn(1.0f, eg)),
                                __fmul_rn(__fdiv_rn(ar, gmb), __fsub_rn(eg, eb)));
        float term3 = __fmul_rn(__fmul_rn(__fdiv_rn(__fmul_rn(bet, U0), gmb),
                                          __fsub_rn(egs, ebs)), S);
        float ts = __fadd_rn(__fadd_rn(__fmul_rn(term1, oneMS), __fmul_rn(ag, S)), term3);

        out[v] = tu;
        out[n + v] = ts;
    }
}

// ---------------- launch ----------------
extern "C" void kernel_launch(void* const* d_in, const int* in_sizes, int n_in,
                              void* d_out, int out_size) {
    int off = (n_in >= 28) ? 0 : -1;
    const float* x    = (const float*)d_in[0];
    const int*   ei   = (const int*)d_in[1];
    const float* W0   = (const float*)d_in[3 + off];
    const float* as0  = (const float*)d_in[4 + off];
    const float* ad0  = (const float*)d_in[5 + off];
    const float* b0   = (const float*)d_in[6 + off];
    const float* W1   = (const float*)d_in[7 + off];
    const float* as1  = (const float*)d_in[8 + off];
    const float* ad1  = (const float*)d_in[9 + off];
    const float* b1   = (const float*)d_in[10 + off];
    const float* W2   = (const float*)d_in[11 + off];
    const float* as2  = (const float*)d_in[12 + off];
    const float* ad2  = (const float*)d_in[13 + off];
    const float* b2   = (const float*)d_in[14 + off];
    const float* bng0 = (const float*)d_in[15 + off];
    const float* bnb0 = (const float*)d_in[16 + off];
    const float* bnm0 = (const float*)d_in[17 + off];
    const float* bnv0 = (const float*)d_in[18 + off];
    const float* bng1 = (const float*)d_in[19 + off];
    const float* bnb1 = (const float*)d_in[20 + off];
    const float* bnm1 = (const float*)d_in[21 + off];
    const float* bnv1 = (const float*)d_in[22 + off];
    const float* kk   = (const float*)d_in[23 + off];
    const float* dd   = (const float*)d_in[24 + off];
    const float* t00  = (const float*)d_in[25 + off];
    const float* u00  = (const float*)d_in[26 + off];
    const float* t    = (const float*)d_in[27 + off];
    float* out = (float*)d_out;

    int n = in_sizes[0] / 2;
    int e = in_sizes[1] / 2;
    int m = e + n;

    const int B = 256;
    auto nb = [](long long x, int b) { return (int)((x + b - 1) / b); };
    int nwb = nb((long long)n * 32, B);   // warp-per-node grids

    cudaFuncSetAttribute(k_gemm1, cudaFuncAttributeMaxDynamicSharedMemorySize, GEMM_SMEM);

    // CSR build
    k_zero<<<nb(n, B), B>>>(n);
    k_edges_count<<<nb(m, B), B>>>(ei, e, m);
    k_scan<<<1, 1024>>>(n, m);
    k_fill<<<nb(m, B), B>>>(m);

    // ---- layer 0 ----
    k_h_l0<<<nb((long long)n * 512, B), B>>>(x, W0, n);
    k_scoreW<<<nwb, B>>>(as0, ad0, n);
    k_smax<<<nwb, B>>>(n);
    k_gath<<<nwb, B>>>(b0, bng0, bnb0, bnm0, bnv0, 0, n);

    // ---- layer 1 ----
    {
        dim3 grid(nb(n, 32), 4);
        k_gemm1<<<grid, 256, GEMM_SMEM>>>(W1, n);
    }
    k_scoreW<<<nwb, B>>>(as1, ad1, n);
    k_smax<<<nwb, B>>>(n);
    k_gath<<<nwb, B>>>(b1, bng1, bnb1, bnm1, bnv1, 1, n);

    // ---- layer 2 + epilogue ----
    k_l2<<<nwb, B>>>(W2, as2, ad2, n);
    k_smax2epi<<<nwb, B>>>(b2, kk, dd, t00, u00, t, out, n);
}

// round 8
// speedup vs baseline: 18.0949x; 1.2094x over previous
#include <cuda_runtime.h>
#include <math.h>

#define NN 20000
#define EE 320000
#define MMX (EE + NN)
#define FULL 0xffffffffu

// ---------------- scratch ----------------
__device__ float g_z[NN * 512];          // layer-1 aggregated z (pre-divided by sum)
__device__ float g_xa[NN * 128];
__device__ float g_xb[NN * 128];
__device__ float g_s[NN * 4];
__device__ float g_d[NN * 4];
__device__ float g_h2[NN * 3];
__device__ int g_esrc[MMX];
__device__ int g_edst[MMX];
__device__ int g_deg[NN];
__device__ int g_rowptr[NN + 1];
__device__ int g_cursor[NN];
__device__ int g_csrs[MMX];              // CSR by dst: src node per slot
__device__ float g_A0[16];               // layer0: As(h,i) [0..7], Ad(h,i) [8..15]
__device__ float g_ws[512];              // layer1: w~s_h[k] = W1_h^T as_h
__device__ float g_wd[512];

// ---------------- accurate exp/expm1/elu ----------------
__device__ __forceinline__ float exp_acc(float x) {
    x = fminf(fmaxf(x, -87.0f), 87.0f);
    float kf = rintf(__fmul_rn(x, 1.4426950408889634f));
    float r = __fmaf_rn(kf, -0.69314718246459960938f, x);
    r = __fmaf_rn(kf, 1.9046542743622637e-9f, r);
    float p = 1.9841269841269841e-4f;
    p = __fmaf_rn(p, r, 1.3888888888888889e-3f);
    p = __fmaf_rn(p, r, 8.3333333333333332e-3f);
    p = __fmaf_rn(p, r, 4.1666666666666664e-2f);
    p = __fmaf_rn(p, r, 1.6666666666666666e-1f);
    p = __fmaf_rn(p, r, 0.5f);
    p = __fmaf_rn(p, r, 1.0f);
    p = __fmaf_rn(p, r, 1.0f);
    int ik = (int)kf;
    float s = __int_as_float((ik + 127) << 23);
    return __fmul_rn(p, s);
}
__device__ __forceinline__ float expm1_acc(float x) {
    if (x < -0.34657359f) return __fadd_rn(exp_acc(x), -1.0f);
    float p = 1.9841269841269841e-4f;
    p = __fmaf_rn(p, x, 1.3888888888888889e-3f);
    p = __fmaf_rn(p, x, 8.3333333333333332e-3f);
    p = __fmaf_rn(p, x, 4.1666666666666664e-2f);
    p = __fmaf_rn(p, x, 1.6666666666666666e-1f);
    p = __fmaf_rn(p, x, 0.5f);
    p = __fmaf_rn(p, x, 1.0f);
    return __fmul_rn(p, x);
}
__device__ __forceinline__ float elu_acc(float x) {
    return x > 0.f ? x : expm1_acc(x);
}
__device__ __forceinline__ float lrelu(float x) {
    return x >= 0.f ? x : 0.2f * x;
}

// ---------------- CSR build ----------------
__global__ void k_zero(int n) {
    int i = blockIdx.x * blockDim.x + threadIdx.x;
    if (i < n) g_deg[i] = 0;
}
__global__ void k_edges_count(const int* __restrict__ ei, int e, int m) {
    int i = blockIdx.x * blockDim.x + threadIdx.x;
    if (i >= m) return;
    int s, d;
    if (i < e) { s = ei[i]; d = ei[e + i]; }
    else       { s = i - e; d = i - e; }
    g_esrc[i] = s;
    g_edst[i] = d;
    atomicAdd(&g_deg[d], 1);
}
__global__ void k_scan(int n, int m) {
    __shared__ int wsum[32];
    int t = threadIdx.x;
    int lane = t & 31, wid = t >> 5;
    int chunk = (n + 1023) / 1024;
    int b0 = t * chunk;
    int b1 = min(b0 + chunk, n);
    int s = 0;
    for (int i = b0; i < b1; i++) s += g_deg[i];
    int v = s;
#pragma unroll
    for (int o = 1; o < 32; o <<= 1) {
        int u = __shfl_up_sync(FULL, v, o);
        if (lane >= o) v += u;
    }
    if (lane == 31) wsum[wid] = v;
    __syncthreads();
    if (wid == 0) {
        int w = wsum[lane];
#pragma unroll
        for (int o = 1; o < 32; o <<= 1) {
            int u = __shfl_up_sync(FULL, w, o);
            if (lane >= o) w += u;
        }
        wsum[lane] = w;
    }
    __syncthreads();
    int run = (v - s) + (wid > 0 ? wsum[wid - 1] : 0);
    for (int i = b0; i < b1; i++) {
        g_rowptr[i] = run;
        g_cursor[i] = run;
        run += g_deg[i];
    }
    if (t == 0) g_rowptr[n] = m;
}
__global__ void k_fill(int m) {
    int i = blockIdx.x * blockDim.x + threadIdx.x;
    if (i < m) {
        int pos = atomicAdd(&g_cursor[g_edst[i]], 1);
        g_csrs[pos] = g_esrc[i];
    }
}

// ---------------- precompute projected attention vectors ----------------
// g_ws[h*128+k] = sum_c as1[h*128+c] * W1[(h*128+c)*128+k]  (same for g_wd/ad1)
// g_A0[h*2+i]   = sum_c as0[h*128+c] * W0[(h*128+c)*2+i]; [8..] with ad0
__global__ void k_pre(const float* __restrict__ W0, const float* __restrict__ as0,
                      const float* __restrict__ ad0,
                      const float* __restrict__ W1, const float* __restrict__ as1,
                      const float* __restrict__ ad1) {
    int t = threadIdx.x;   // 1024 threads
    if (t < 512) {
        int h = t >> 7, k = t & 127;
        float acc = 0.f;
        for (int c = 0; c < 128; c++)
            acc = __fmaf_rn(as1[h * 128 + c], W1[(size_t)(h * 128 + c) * 128 + k], acc);
        g_ws[t] = acc;
    } else {
        int u = t - 512;
        int h = u >> 7, k = u & 127;
        float acc = 0.f;
        for (int c = 0; c < 128; c++)
            acc = __fmaf_rn(ad1[h * 128 + c], W1[(size_t)(h * 128 + c) * 128 + k], acc);
        g_wd[u] = acc;
    }
    if (t < 16) {
        int h = t & 3, i = (t >> 2) & 1;
        const float* a = (t < 8) ? as0 : ad0;
        float acc = 0.f;
        for (int c = 0; c < 128; c++)
            acc = __fmaf_rn(a[h * 128 + c], W0[(h * 128 + c) * 2 + i], acc);
        g_A0[(t < 8 ? 0 : 8) + h * 2 + i] = acc;
    }
}

// ---------------- layer 0 scores: s[v,h] = x[v] . As_h ----------------
__global__ void k_score0(const float* __restrict__ x, int n) {
    int v = blockIdx.x * blockDim.x + threadIdx.x;
    if (v >= n) return;
    float x0 = x[2 * v], x1 = x[2 * v + 1];
    float4 s, d;
    s.x = __fmaf_rn(x0, g_A0[0], x1 * g_A0[1]);
    s.y = __fmaf_rn(x0, g_A0[2], x1 * g_A0[3]);
    s.z = __fmaf_rn(x0, g_A0[4], x1 * g_A0[5]);
    s.w = __fmaf_rn(x0, g_A0[6], x1 * g_A0[7]);
    d.x = __fmaf_rn(x0, g_A0[8],  x1 * g_A0[9]);
    d.y = __fmaf_rn(x0, g_A0[10], x1 * g_A0[11]);
    d.z = __fmaf_rn(x0, g_A0[12], x1 * g_A0[13]);
    d.w = __fmaf_rn(x0, g_A0[14], x1 * g_A0[15]);
    *(float4*)&g_s[v * 4] = s;
    *(float4*)&g_d[v * 4] = d;
}

// ---------------- layer 0: fused softmax + rank-2 aggregate + finalize ----------------
__global__ void k_l0agg(const float* __restrict__ x, const float* __restrict__ W0,
                        const float* __restrict__ bias,
                        const float* __restrict__ bng, const float* __restrict__ bnb,
                        const float* __restrict__ bnm, const float* __restrict__ bnv, int n) {
    int v = (blockIdx.x * blockDim.x + threadIdx.x) >> 5;
    int lane = threadIdx.x & 31;
    if (v >= n) return;
    int beg = g_rowptr[v], end = g_rowptr[v + 1];
    float4 dv = *(const float4*)&g_d[v * 4];

    float m0 = -1e30f, m1 = -1e30f, m2 = -1e30f, m3 = -1e30f;
    for (int idx = beg + lane; idx < end; idx += 32) {
        int s = g_csrs[idx];
        float4 sv = *(const float4*)&g_s[s * 4];
        m0 = fmaxf(m0, lrelu(sv.x + dv.x));
        m1 = fmaxf(m1, lrelu(sv.y + dv.y));
        m2 = fmaxf(m2, lrelu(sv.z + dv.z));
        m3 = fmaxf(m3, lrelu(sv.w + dv.w));
    }
#pragma unroll
    for (int o = 16; o > 0; o >>= 1) {
        m0 = fmaxf(m0, __shfl_xor_sync(FULL, m0, o));
        m1 = fmaxf(m1, __shfl_xor_sync(FULL, m1, o));
        m2 = fmaxf(m2, __shfl_xor_sync(FULL, m2, o));
        m3 = fmaxf(m3, __shfl_xor_sync(FULL, m3, o));
    }

    float s0 = 0.f, s1 = 0.f, s2 = 0.f, s3 = 0.f;
    float zx0 = 0.f, zx1 = 0.f, zx2 = 0.f, zx3 = 0.f;
    float zy0 = 0.f, zy1 = 0.f, zy2 = 0.f, zy3 = 0.f;
    for (int idx = beg + lane; idx < end; idx += 32) {
        int s = g_csrs[idx];
        float4 sv = *(const float4*)&g_s[s * 4];
        float p0 = exp_acc(lrelu(sv.x + dv.x) - m0);
        float p1 = exp_acc(lrelu(sv.y + dv.y) - m1);
        float p2 = exp_acc(lrelu(sv.z + dv.z) - m2);
        float p3 = exp_acc(lrelu(sv.w + dv.w) - m3);
        s0 += p0; s1 += p1; s2 += p2; s3 += p3;
        float2 xv = *(const float2*)&x[2 * s];
        zx0 = __fmaf_rn(p0, xv.x, zx0); zy0 = __fmaf_rn(p0, xv.y, zy0);
        zx1 = __fmaf_rn(p1, xv.x, zx1); zy1 = __fmaf_rn(p1, xv.y, zy1);
        zx2 = __fmaf_rn(p2, xv.x, zx2); zy2 = __fmaf_rn(p2, xv.y, zy2);
        zx3 = __fmaf_rn(p3, xv.x, zx3); zy3 = __fmaf_rn(p3, xv.y, zy3);
    }
#pragma unroll
    for (int o = 16; o > 0; o >>= 1) {
        s0 += __shfl_xor_sync(FULL, s0, o);  s1 += __shfl_xor_sync(FULL, s1, o);
        s2 += __shfl_xor_sync(FULL, s2, o);  s3 += __shfl_xor_sync(FULL, s3, o);
        zx0 += __shfl_xor_sync(FULL, zx0, o); zx1 += __shfl_xor_sync(FULL, zx1, o);
        zx2 += __shfl_xor_sync(FULL, zx2, o); zx3 += __shfl_xor_sync(FULL, zx3, o);
        zy0 += __shfl_xor_sync(FULL, zy0, o); zy1 += __shfl_xor_sync(FULL, zy1, o);
        zy2 += __shfl_xor_sync(FULL, zy2, o); zy3 += __shfl_xor_sync(FULL, zy3, o);
    }
    float d0 = __fadd_rn(s0, 1e-16f);
    float d1 = __fadd_rn(s1, 1e-16f);
    float d2 = __fadd_rn(s2, 1e-16f);
    float d3 = __fadd_rn(s3, 1e-16f);
    float ZX[4] = {zx0, zx1, zx2, zx3};
    float ZY[4] = {zy0, zy1, zy2, zy3};
    float DD[4] = {d0, d1, d2, d3};

    int c = lane * 4;
    float vals[4];
#pragma unroll
    for (int j = 0; j < 4; j++) {
        int cc = c + j;
        float a = 0.f;
#pragma unroll
        for (int h = 0; h < 4; h++) {
            float w0 = W0[(h * 128 + cc) * 2];
            float w1 = W0[(h * 128 + cc) * 2 + 1];
            float tmp = __fmaf_rn(w0, ZX[h], __fmul_rn(w1, ZY[h]));
            a = __fadd_rn(a, __fdiv_rn(tmp, DD[h]));
        }
        float val = __fmul_rn(a, 0.25f);
        val = __fadd_rn(val, bias[cc]);
        val = elu_acc(val);
        float inv = __frsqrt_rn(__fadd_rn(bnv[cc], 1e-5f));
        val = __fadd_rn(__fmul_rn(__fmul_rn(__fsub_rn(val, bnm[cc]), inv), bng[cc]), bnb[cc]);
        vals[j] = val;
    }
    *(float4*)&g_xa[(size_t)v * 128 + c] = make_float4(vals[0], vals[1], vals[2], vals[3]);
}

// ---------------- layer 1 scores: s[v,h] = xa[v] . w~s_h ----------------
__global__ void k_score1(int n) {
    int v = (blockIdx.x * blockDim.x + threadIdx.x) >> 5;
    int lane = threadIdx.x & 31;
    if (v >= n) return;
    float4 xv = *(const float4*)&g_xa[(size_t)v * 128 + lane * 4];
    float sp[4], dp[4];
#pragma unroll
    for (int hd = 0; hd < 4; hd++) {
        float4 wv = *(const float4*)&g_ws[hd * 128 + lane * 4];
        float4 uv = *(const float4*)&g_wd[hd * 128 + lane * 4];
        float s = xv.x * wv.x + xv.y * wv.y + xv.z * wv.z + xv.w * wv.w;
        float d = xv.x * uv.x + xv.y * uv.y + xv.z * uv.z + xv.w * uv.w;
#pragma unroll
        for (int o = 16; o > 0; o >>= 1) {
            s += __shfl_xor_sync(FULL, s, o);
            d += __shfl_xor_sync(FULL, d, o);
        }
        sp[hd] = s;
        dp[hd] = d;
    }
    if (lane == 0) {
        *(float4*)&g_s[v * 4] = make_float4(sp[0], sp[1], sp[2], sp[3]);
        *(float4*)&g_d[v * 4] = make_float4(dp[0], dp[1], dp[2], dp[3]);
    }
}

// ---------------- layer 1: fused softmax + z-aggregate (z pre-divided by sum) ----------------
__global__ void k_agg1(int n) {
    int v = (blockIdx.x * blockDim.x + threadIdx.x) >> 5;
    int lane = threadIdx.x & 31;
    if (v >= n) return;
    int beg = g_rowptr[v], end = g_rowptr[v + 1];
    float4 dv = *(const float4*)&g_d[v * 4];

    float m0 = -1e30f, m1 = -1e30f, m2 = -1e30f, m3 = -1e30f;
    for (int idx = beg + lane; idx < end; idx += 32) {
        int s = g_csrs[idx];
        float4 sv = *(const float4*)&g_s[s * 4];
        m0 = fmaxf(m0, lrelu(sv.x + dv.x));
        m1 = fmaxf(m1, lrelu(sv.y + dv.y));
        m2 = fmaxf(m2, lrelu(sv.z + dv.z));
        m3 = fmaxf(m3, lrelu(sv.w + dv.w));
    }
#pragma unroll
    for (int o = 16; o > 0; o >>= 1) {
        m0 = fmaxf(m0, __shfl_xor_sync(FULL, m0, o));
        m1 = fmaxf(m1, __shfl_xor_sync(FULL, m1, o));
        m2 = fmaxf(m2, __shfl_xor_sync(FULL, m2, o));
        m3 = fmaxf(m3, __shfl_xor_sync(FULL, m3, o));
    }

    float acc[16];
#pragma unroll
    for (int i = 0; i < 16; i++) acc[i] = 0.f;
    float s0 = 0.f, s1 = 0.f, s2 = 0.f, s3 = 0.f;

    for (int base = beg; base < end; base += 32) {
        int idx = base + lane;
        int sv = 0;
        float p0 = 0.f, p1 = 0.f, p2 = 0.f, p3 = 0.f;
        if (idx < end) {
            sv = g_csrs[idx];
            float4 ss = *(const float4*)&g_s[sv * 4];
            p0 = exp_acc(lrelu(ss.x + dv.x) - m0);
            p1 = exp_acc(lrelu(ss.y + dv.y) - m1);
            p2 = exp_acc(lrelu(ss.z + dv.z) - m2);
            p3 = exp_acc(lrelu(ss.w + dv.w) - m3);
            s0 += p0; s1 += p1; s2 += p2; s3 += p3;
        }
        int cnt = min(32, end - base);
        for (int t = 0; t < cnt; t++) {
            int s = __shfl_sync(FULL, sv, t);
            float q0 = __shfl_sync(FULL, p0, t);
            float q1 = __shfl_sync(FULL, p1, t);
            float q2 = __shfl_sync(FULL, p2, t);
            float q3 = __shfl_sync(FULL, p3, t);
            float4 xv = *(const float4*)&g_xa[(size_t)s * 128 + lane * 4];
            acc[0]  = __fmaf_rn(q0, xv.x, acc[0]);  acc[1]  = __fmaf_rn(q0, xv.y, acc[1]);
            acc[2]  = __fmaf_rn(q0, xv.z, acc[2]);  acc[3]  = __fmaf_rn(q0, xv.w, acc[3]);
            acc[4]  = __fmaf_rn(q1, xv.x, acc[4]);  acc[5]  = __fmaf_rn(q1, xv.y, acc[5]);
            acc[6]  = __fmaf_rn(q1, xv.z, acc[6]);  acc[7]  = __fmaf_rn(q1, xv.w, acc[7]);
            acc[8]  = __fmaf_rn(q2, xv.x, acc[8]);  acc[9]  = __fmaf_rn(q2, xv.y, acc[9]);
            acc[10] = __fmaf_rn(q2, xv.z, acc[10]); acc[11] = __fmaf_rn(q2, xv.w, acc[11]);
            acc[12] = __fmaf_rn(q3, xv.x, acc[12]); acc[13] = __fmaf_rn(q3, xv.y, acc[13]);
            acc[14] = __fmaf_rn(q3, xv.z, acc[14]); acc[15] = __fmaf_rn(q3, xv.w, acc[15]);
        }
    }
#pragma unroll
    for (int o = 16; o > 0; o >>= 1) {
        s0 += __shfl_xor_sync(FULL, s0, o);
        s1 += __shfl_xor_sync(FULL, s1, o);
        s2 += __shfl_xor_sync(FULL, s2, o);
        s3 += __shfl_xor_sync(FULL, s3, o);
    }
    float r0 = __fdiv_rn(1.0f, __fadd_rn(s0, 1e-16f));
    float r1 = __fdiv_rn(1.0f, __fadd_rn(s1, 1e-16f));
    float r2 = __fdiv_rn(1.0f, __fadd_rn(s2, 1e-16f));
    float r3 = __fdiv_rn(1.0f, __fadd_rn(s3, 1e-16f));

    float* zp = &g_z[(size_t)v * 512 + lane * 4];
    *(float4*)&zp[0]   = make_float4(acc[0] * r0,  acc[1] * r0,  acc[2] * r0,  acc[3] * r0);
    *(float4*)&zp[128] = make_float4(acc[4] * r1,  acc[5] * r1,  acc[6] * r1,  acc[7] * r1);
    *(float4*)&zp[256] = make_float4(acc[8] * r2,  acc[9] * r2,  acc[10] * r2, acc[11] * r2);
    *(float4*)&zp[384] = make_float4(acc[12] * r3, acc[13] * r3, acc[14] * r3, acc[15] * r3);
}

// ---------------- layer 1: post-aggregation GEMM + finalize -> xb ----------------
// xb[v][c] = BN(ELU(0.25 * sum_h (W1_h . z~_h[v])[c] + b1[c]))
#define GEMM_SMEM ((128 * 132 + 128 * 36) * 4)
__global__ void k_gemmpost(const float* __restrict__ W1, const float* __restrict__ bias,
                           const float* __restrict__ bng, const float* __restrict__ bnb,
                           const float* __restrict__ bnm, const float* __restrict__ bnv, int n) {
    extern __shared__ float sm[];
    float* w_s = sm;               // w_s[k*132 + c]
    float* z_s = sm + 128 * 132;   // z_s[k*36 + nl]
    int tid = threadIdx.x;
    int node0 = blockIdx.x * 32;

    int jt = (tid & 31) * 4;   // c
    int nt = (tid >> 5) * 4;   // node
    float acc[4][4];
#pragma unroll
    for (int r = 0; r < 4; r++)
#pragma unroll
        for (int c = 0; c < 4; c++) acc[r][c] = 0.f;

    for (int h = 0; h < 4; h++) {
        for (int idx = tid; idx < 128 * 128; idx += 256) {
            int j = idx >> 7, k = idx & 127;
            w_s[k * 132 + j] = W1[(size_t)(h * 128 + j) * 128 + k];
        }
        for (int idx = tid; idx < 32 * 128; idx += 256) {
            int nl = idx >> 7, k = idx & 127;
            int nd = node0 + nl;
            z_s[k * 36 + nl] = (nd < n) ? g_z[(size_t)nd * 512 + h * 128 + k] : 0.f;
        }
        __syncthreads();

#pragma unroll 8
        for (int k = 0; k < 128; k++) {
            float4 xv = *(const float4*)&z_s[k * 36 + nt];
            float4 wv = *(const float4*)&w_s[k * 132 + jt];
            acc[0][0] = __fmaf_rn(xv.x, wv.x, acc[0][0]); acc[0][1] = __fmaf_rn(xv.x, wv.y, acc[0][1]);
            acc[0][2] = __fmaf_rn(xv.x, wv.z, acc[0][2]); acc[0][3] = __fmaf_rn(xv.x, wv.w, acc[0][3]);
            acc[1][0] = __fmaf_rn(xv.y, wv.x, acc[1][0]); acc[1][1] = __fmaf_rn(xv.y, wv.y, acc[1][1]);
            acc[1][2] = __fmaf_rn(xv.y, wv.z, acc[1][2]); acc[1][3] = __fmaf_rn(xv.y, wv.w, acc[1][3]);
            acc[2][0] = __fmaf_rn(xv.z, wv.x, acc[2][0]); acc[2][1] = __fmaf_rn(xv.z, wv.y, acc[2][1]);
            acc[2][2] = __fmaf_rn(xv.z, wv.z, acc[2][2]); acc[2][3] = __fmaf_rn(xv.z, wv.w, acc[2][3]);
            acc[3][0] = __fmaf_rn(xv.w, wv.x, acc[3][0]); acc[3][1] = __fmaf_rn(xv.w, wv.y, acc[3][1]);
            acc[3][2] = __fmaf_rn(xv.w, wv.z, acc[3][2]); acc[3][3] = __fmaf_rn(xv.w, wv.w, acc[3][3]);
        }
        __syncthreads();
    }

    float bv[4], gv[4], bb[4], mv[4], vv[4];
#pragma unroll
    for (int i = 0; i < 4; i++) {
        bv[i] = bias[jt + i]; gv[i] = bng[jt + i]; bb[i] = bnb[jt + i];
        mv[i] = bnm[jt + i];  vv[i] = bnv[jt + i];
    }
#pragma unroll
    for (int r = 0; r < 4; r++) {
        int nd = node0 + nt + r;
        if (nd >= n) continue;
        float vals[4];
#pragma unroll
        for (int c = 0; c < 4; c++) {
            float val = __fmul_rn(acc[r][c], 0.25f);
            val = __fadd_rn(val, bv[c]);
            val = elu_acc(val);
            float inv = __frsqrt_rn(__fadd_rn(vv[c], 1e-5f));
            val = __fadd_rn(__fmul_rn(__fmul_rn(__fsub_rn(val, mv[c]), inv), gv[c]), bb[c]);
            vals[c] = val;
        }
        *(float4*)&g_xb[(size_t)nd * 128 + jt] = make_float4(vals[0], vals[1], vals[2], vals[3]);
    }
}

// ---------------- layer 2: fused h2 + scores ----------------
__global__ void k_l2(const float* __restrict__ W, const float* __restrict__ as_,
                     const float* __restrict__ ad_, int n) {
    int v = (blockIdx.x * blockDim.x + threadIdx.x) >> 5;
    int lane = threadIdx.x & 31;
    if (v >= n) return;
    float4 xv = *(const float4*)&g_xb[(size_t)v * 128 + lane * 4];
    float p[3];
#pragma unroll
    for (int o = 0; o < 3; o++) {
        float4 wv = *(const float4*)&W[o * 128 + lane * 4];
        float pp = __fmaf_rn(xv.x, wv.x, __fmaf_rn(xv.y, wv.y, __fmaf_rn(xv.z, wv.z, xv.w * wv.w)));
#pragma unroll
        for (int off = 16; off > 0; off >>= 1) pp += __shfl_xor_sync(FULL, pp, off);
        p[o] = pp;
    }
    if (lane == 0) {
        g_h2[v * 3 + 0] = p[0];
        g_h2[v * 3 + 1] = p[1];
        g_h2[v * 3 + 2] = p[2];
        g_s[v] = __fmaf_rn(p[0], as_[0], __fmaf_rn(p[1], as_[1], p[2] * as_[2]));
        g_d[v] = __fmaf_rn(p[0], ad_[0], __fmaf_rn(p[1], ad_[1], p[2] * ad_[2]));
    }
}

// ---------------- layer 2: softmax + aggregate + ODE epilogue ----------------
__global__ void k_smax2epi(const float* __restrict__ b2,
                           const float* __restrict__ kk, const float* __restrict__ dd,
                           const float* __restrict__ t00, const float* __restrict__ u00,
                           const float* __restrict__ t, float* __restrict__ out, int n) {
    int v = (blockIdx.x * blockDim.x + threadIdx.x) >> 5;
    int lane = threadIdx.x & 31;
    if (v >= n) return;
    int beg = g_rowptr[v], end = g_rowptr[v + 1];
    float sd = g_d[v];

    float mx = -1e30f;
    for (int idx = beg + lane; idx < end; idx += 32)
        mx = fmaxf(mx, lrelu(g_s[g_csrs[idx]] + sd));
#pragma unroll
    for (int o = 16; o > 0; o >>= 1) mx = fmaxf(mx, __shfl_xor_sync(FULL, mx, o));

    float sum = 0.f, a0 = 0.f, a1 = 0.f, a2 = 0.f;
    for (int idx = beg + lane; idx < end; idx += 32) {
        int s = g_csrs[idx];
        float p = exp_acc(lrelu(g_s[s] + sd) - mx);
        sum += p;
        a0 = __fmaf_rn(p, g_h2[s * 3 + 0], a0);
        a1 = __fmaf_rn(p, g_h2[s * 3 + 1], a1);
        a2 = __fmaf_rn(p, g_h2[s * 3 + 2], a2);
    }
#pragma unroll
    for (int o = 16; o > 0; o >>= 1) {
        sum += __shfl_xor_sync(FULL, sum, o);
        a0 += __shfl_xor_sync(FULL, a0, o);
        a1 += __shfl_xor_sync(FULL, a1, o);
        a2 += __shfl_xor_sync(FULL, a2, o);
    }
    if (lane == 0) {
        float denom = __fadd_rn(sum, 1e-16f);
        float ar  = elu_acc(__fadd_rn(__fdiv_rn(a0, denom), b2[0]));
        float gam = elu_acc(__fadd_rn(__fdiv_rn(a1, denom), b2[1]));
        float bet = elu_acc(__fadd_rn(__fdiv_rn(a2, denom), b2[2]));

        float tt = t[v];
        float K = kk[0], D = dd[0], T0 = t00[0], U0 = u00[0];

        float z = __fmul_rn(K, __fsub_rn(__fsub_rn(tt, T0), D));
        float S = __fdiv_rn(1.0f, __fadd_rn(1.0f, exp_acc(-z)));
        float oneMS = __fsub_rn(1.0f, S);

        float eb  = exp_acc(__fmul_rn(-bet, tt));
        float eg  = exp_acc(__fmul_rn(-gam, tt));
        float tmt0 = __fsub_rn(tt, T0);
        float ebs = exp_acc(__fmul_rn(-bet, tmt0));
        float egs = exp_acc(__fmul_rn(-gam, tmt0));
        float ab = __fdiv_rn(ar, bet);
        float ag = __fdiv_rn(ar, gam);

        float tu = __fadd_rn(
                     __fadd_rn(__fmul_rn(__fmul_rn(ab, __fsub_rn(1.0f, eb)), oneMS),
                               __fmul_rn(ab, S)),
                     __fmul_rn(__fsub_rn(__fmul_rn(U0, ebs), ab), S));

        float gmb = __fsub_rn(gam, bet);
        float term1 = __fadd_rn(__fmul_rn(ag, __fsub_rn(1.0f, eg)),
                                __fmul_rn(__fdiv_rn(ar, gmb), __fsub_rn(eg, eb)));
        float term3 = __fmul_rn(__fmul_rn(__fdiv_rn(__fmul_rn(bet, U0), gmb),
                                          __fsub_rn(egs, ebs)), S);
        float ts = __fadd_rn(__fadd_rn(__fmul_rn(term1, oneMS), __fmul_rn(ag, S)), term3);

        out[v] = tu;
        out[n + v] = ts;
    }
}

// ---------------- launch ----------------
extern "C" void kernel_launch(void* const* d_in, const int* in_sizes, int n_in,
                              void* d_out, int out_size) {
    int off = (n_in >= 28) ? 0 : -1;
    const float* x    = (const float*)d_in[0];
    const int*   ei   = (const int*)d_in[1];
    const float* W0   = (const float*)d_in[3 + off];
    const float* as0  = (const float*)d_in[4 + off];
    const float* ad0  = (const float*)d_in[5 + off];
    const float* b0   = (const float*)d_in[6 + off];
    const float* W1   = (const float*)d_in[7 + off];
    const float* as1  = (const float*)d_in[8 + off];
    const float* ad1  = (const float*)d_in[9 + off];
    const float* b1   = (const float*)d_in[10 + off];
    const float* W2   = (const float*)d_in[11 + off];
    const float* as2  = (const float*)d_in[12 + off];
    const float* ad2  = (const float*)d_in[13 + off];
    const float* b2   = (const float*)d_in[14 + off];
    const float* bng0 = (const float*)d_in[15 + off];
    const float* bnb0 = (const float*)d_in[16 + off];
    const float* bnm0 = (const float*)d_in[17 + off];
    const float* bnv0 = (const float*)d_in[18 + off];
    const float* bng1 = (const float*)d_in[19 + off];
    const float* bnb1 = (const float*)d_in[20 + off];
    const float* bnm1 = (const float*)d_in[21 + off];
    const float* bnv1 = (const float*)d_in[22 + off];
    const float* kk   = (const float*)d_in[23 + off];
    const float* dd   = (const float*)d_in[24 + off];
    const float* t00  = (const float*)d_in[25 + off];
    const float* u00  = (const float*)d_in[26 + off];
    const float* t    = (const float*)d_in[27 + off];
    float* out = (float*)d_out;

    int n = in_sizes[0] / 2;
    int e = in_sizes[1] / 2;
    int m = e + n;

    const int B = 256;
    auto nb = [](long long x_, int b) { return (int)((x_ + b - 1) / b); };
    int nwb = nb((long long)n * 32, B);   // warp-per-node grids

    cudaFuncSetAttribute(k_gemmpost, cudaFuncAttributeMaxDynamicSharedMemorySize, GEMM_SMEM);

    // CSR build + attention-vector precompute
    k_zero<<<nb(n, B), B>>>(n);
    k_edges_count<<<nb(m, B), B>>>(ei, e, m);
    k_scan<<<1, 1024>>>(n, m);
    k_fill<<<nb(m, B), B>>>(m);
    k_pre<<<1, 1024>>>(W0, as0, ad0, W1, as1, ad1);

    // ---- layer 0 (h never materialized) ----
    k_score0<<<nb(n, B), B>>>(x, n);
    k_l0agg<<<nwb, B>>>(x, W0, b0, bng0, bnb0, bnm0, bnv0, n);

    // ---- layer 1 (aggregate z first, project after) ----
    k_score1<<<nwb, B>>>(n);
    k_agg1<<<nwb, B>>>(n);
    k_gemmpost<<<nb(n, 32), 256, GEMM_SMEM>>>(W1, b1, bng1, bnb1, bnm1, bnv1, n);

    // ---- layer 2 + epilogue ----
    k_l2<<<nwb, B>>>(W2, as2, ad2, n);
    k_smax2epi<<<nwb, B>>>(b2, kk, dd, t00, u00, t, out, n);
}

// round 10
// speedup vs baseline: 21.4011x; 1.1827x over previous
#include <cuda_runtime.h>
#include <math.h>
#include <cstdint>

#define NN 20000
#define EE 320000
#define MMX (EE + NN)
#define FULL 0xffffffffu

// ---------------- scratch ----------------
__device__ float g_z[NN * 512];          // layer-1 aggregated z (pre-divided by sum)
__device__ float g_xa[NN * 128];
__device__ float g_xb[NN * 128];
__device__ float g_s[NN * 4];
__device__ float g_d[NN * 4];
__device__ float g_h2[NN * 3];
__device__ int g_esrc[MMX];
__device__ int g_edst[MMX];
__device__ int g_deg[NN];
__device__ int g_rowptr[NN + 1];
__device__ int g_cursor[NN];
__device__ int g_csrs[MMX];              // CSR by dst: src node per slot
__device__ float g_A0[16];               // layer0: As(h,i) [0..7], Ad(h,i) [8..15]
__device__ float g_ws[512];              // layer1: w~s_h[k] = W1_h^T as_h
__device__ float g_wd[512];

// ---------------- accurate exp/expm1/elu ----------------
__device__ __forceinline__ float exp_acc(float x) {
    x = fminf(fmaxf(x, -87.0f), 87.0f);
    float kf = rintf(__fmul_rn(x, 1.4426950408889634f));
    float r = __fmaf_rn(kf, -0.69314718246459960938f, x);
    r = __fmaf_rn(kf, 1.9046542743622637e-9f, r);
    float p = 1.9841269841269841e-4f;
    p = __fmaf_rn(p, r, 1.3888888888888889e-3f);
    p = __fmaf_rn(p, r, 8.3333333333333332e-3f);
    p = __fmaf_rn(p, r, 4.1666666666666664e-2f);
    p = __fmaf_rn(p, r, 1.6666666666666666e-1f);
    p = __fmaf_rn(p, r, 0.5f);
    p = __fmaf_rn(p, r, 1.0f);
    p = __fmaf_rn(p, r, 1.0f);
    int ik = (int)kf;
    float s = __int_as_float((ik + 127) << 23);
    return __fmul_rn(p, s);
}
__device__ __forceinline__ float expm1_acc(float x) {
    if (x < -0.34657359f) return __fadd_rn(exp_acc(x), -1.0f);
    float p = 1.9841269841269841e-4f;
    p = __fmaf_rn(p, x, 1.3888888888888889e-3f);
    p = __fmaf_rn(p, x, 8.3333333333333332e-3f);
    p = __fmaf_rn(p, x, 4.1666666666666664e-2f);
    p = __fmaf_rn(p, x, 1.6666666666666666e-1f);
    p = __fmaf_rn(p, x, 0.5f);
    p = __fmaf_rn(p, x, 1.0f);
    return __fmul_rn(p, x);
}
__device__ __forceinline__ float elu_acc(float x) {
    return x > 0.f ? x : expm1_acc(x);
}
__device__ __forceinline__ float lrelu(float x) {
    return x >= 0.f ? x : 0.2f * x;
}
__device__ __forceinline__ float tf32r(float x) {
    float r;
    asm("cvt.rna.tf32.f32 %0, %1;" : "=f"(r) : "f"(x));
    return r;
}

// ---------------- warp mma: m16n8k8 tf32 ----------------
__device__ __forceinline__ void mma_tf32(float* c, const uint32_t* a, const uint32_t* b) {
    asm volatile(
        "mma.sync.aligned.m16n8k8.row.col.f32.tf32.tf32.f32 "
        "{%0,%1,%2,%3}, {%4,%5,%6,%7}, {%8,%9}, {%0,%1,%2,%3};"
        : "+f"(c[0]), "+f"(c[1]), "+f"(c[2]), "+f"(c[3])
        : "r"(a[0]), "r"(a[1]), "r"(a[2]), "r"(a[3]), "r"(b[0]), "r"(b[1]));
}

// ---------------- CSR build ----------------
__global__ void k_zero(int n) {
    int i = blockIdx.x * blockDim.x + threadIdx.x;
    if (i < n) g_deg[i] = 0;
}
__global__ void k_edges_count(const int* __restrict__ ei, int e, int m) {
    int i = blockIdx.x * blockDim.x + threadIdx.x;
    if (i >= m) return;
    int s, d;
    if (i < e) { s = ei[i]; d = ei[e + i]; }
    else       { s = i - e; d = i - e; }
    g_esrc[i] = s;
    g_edst[i] = d;
    atomicAdd(&g_deg[d], 1);
}
__global__ void k_scan(int n, int m) {
    __shared__ int wsum[32];
    int t = threadIdx.x;
    int lane = t & 31, wid = t >> 5;
    int chunk = (n + 1023) / 1024;
    int b0 = t * chunk;
    int b1 = min(b0 + chunk, n);
    int s = 0;
    for (int i = b0; i < b1; i++) s += g_deg[i];
    int v = s;
#pragma unroll
    for (int o = 1; o < 32; o <<= 1) {
        int u = __shfl_up_sync(FULL, v, o);
        if (lane >= o) v += u;
    }
    if (lane == 31) wsum[wid] = v;
    __syncthreads();
    if (wid == 0) {
        int w = wsum[lane];
#pragma unroll
        for (int o = 1; o < 32; o <<= 1) {
            int u = __shfl_up_sync(FULL, w, o);
            if (lane >= o) w += u;
        }
        wsum[lane] = w;
    }
    __syncthreads();
    int run = (v - s) + (wid > 0 ? wsum[wid - 1] : 0);
    for (int i = b0; i < b1; i++) {
        g_rowptr[i] = run;
        g_cursor[i] = run;
        run += g_deg[i];
    }
    if (t == 0) g_rowptr[n] = m;
}
__global__ void k_fill(int m) {
    int i = blockIdx.x * blockDim.x + threadIdx.x;
    if (i < m) {
        int pos = atomicAdd(&g_cursor[g_edst[i]], 1);
        g_csrs[pos] = g_esrc[i];
    }
}

// ---------------- precompute projected attention vectors ----------------
__global__ void k_pre(const float* __restrict__ W0, const float* __restrict__ as0,
                      const float* __restrict__ ad0,
                      const float* __restrict__ W1, const float* __restrict__ as1,
                      const float* __restrict__ ad1) {
    int t = threadIdx.x;
    if (t < 512) {
        int h = t >> 7, k = t & 127;
        float acc = 0.f;
        for (int c = 0; c < 128; c++)
            acc = __fmaf_rn(as1[h * 128 + c], W1[(size_t)(h * 128 + c) * 128 + k], acc);
        g_ws[t] = acc;
    } else {
        int u = t - 512;
        int h = u >> 7, k = u & 127;
        float acc = 0.f;
        for (int c = 0; c < 128; c++)
            acc = __fmaf_rn(ad1[h * 128 + c], W1[(size_t)(h * 128 + c) * 128 + k], acc);
        g_wd[u] = acc;
    }
    if (t < 16) {
        int h = t & 3, i = (t >> 2) & 1;
        const float* a = (t < 8) ? as0 : ad0;
        float acc = 0.f;
        for (int c = 0; c < 128; c++)
            acc = __fmaf_rn(a[h * 128 + c], W0[(h * 128 + c) * 2 + i], acc);
        g_A0[(t < 8 ? 0 : 8) + h * 2 + i] = acc;
    }
}

// ---------------- layer 0 scores ----------------
__global__ void k_score0(const float* __restrict__ x, int n) {
    int v = blockIdx.x * blockDim.x + threadIdx.x;
    if (v >= n) return;
    float x0 = x[2 * v], x1 = x[2 * v + 1];
    float4 s, d;
    s.x = __fmaf_rn(x0, g_A0[0], x1 * g_A0[1]);
    s.y = __fmaf_rn(x0, g_A0[2], x1 * g_A0[3]);
    s.z = __fmaf_rn(x0, g_A0[4], x1 * g_A0[5]);
    s.w = __fmaf_rn(x0, g_A0[6], x1 * g_A0[7]);
    d.x = __fmaf_rn(x0, g_A0[8],  x1 * g_A0[9]);
    d.y = __fmaf_rn(x0, g_A0[10], x1 * g_A0[11]);
    d.z = __fmaf_rn(x0, g_A0[12], x1 * g_A0[13]);
    d.w = __fmaf_rn(x0, g_A0[14], x1 * g_A0[15]);
    *(float4*)&g_s[v * 4] = s;
    *(float4*)&g_d[v * 4] = d;
}

// ---------------- layer 0: fused softmax + rank-2 aggregate + finalize ----------------
__global__ void k_l0agg(const float* __restrict__ x, const float* __restrict__ W0,
                        const float* __restrict__ bias,
                        const float* __restrict__ bng, const float* __restrict__ bnb,
                        const float* __restrict__ bnm, const float* __restrict__ bnv, int n) {
    int v = (blockIdx.x * blockDim.x + threadIdx.x) >> 5;
    int lane = threadIdx.x & 31;
    if (v >= n) return;
    int beg = g_rowptr[v], end = g_rowptr[v + 1];
    float4 dv = *(const float4*)&g_d[v * 4];

    float m0 = -1e30f, m1 = -1e30f, m2 = -1e30f, m3 = -1e30f;
    for (int idx = beg + lane; idx < end; idx += 32) {
        int s = g_csrs[idx];
        float4 sv = *(const float4*)&g_s[s * 4];
        m0 = fmaxf(m0, lrelu(sv.x + dv.x));
        m1 = fmaxf(m1, lrelu(sv.y + dv.y));
        m2 = fmaxf(m2, lrelu(sv.z + dv.z));
        m3 = fmaxf(m3, lrelu(sv.w + dv.w));
    }
#pragma unroll
    for (int o = 16; o > 0; o >>= 1) {
        m0 = fmaxf(m0, __shfl_xor_sync(FULL, m0, o));
        m1 = fmaxf(m1, __shfl_xor_sync(FULL, m1, o));
        m2 = fmaxf(m2, __shfl_xor_sync(FULL, m2, o));
        m3 = fmaxf(m3, __shfl_xor_sync(FULL, m3, o));
    }

    float s0 = 0.f, s1 = 0.f, s2 = 0.f, s3 = 0.f;
    float zx0 = 0.f, zx1 = 0.f, zx2 = 0.f, zx3 = 0.f;
    float zy0 = 0.f, zy1 = 0.f, zy2 = 0.f, zy3 = 0.f;
    for (int idx = beg + lane; idx < end; idx += 32) {
        int s = g_csrs[idx];
        float4 sv = *(const float4*)&g_s[s * 4];
        float p0 = exp_acc(lrelu(sv.x + dv.x) - m0);
        float p1 = exp_acc(lrelu(sv.y + dv.y) - m1);
        float p2 = exp_acc(lrelu(sv.z + dv.z) - m2);
        float p3 = exp_acc(lrelu(sv.w + dv.w) - m3);
        s0 += p0; s1 += p1; s2 += p2; s3 += p3;
        float2 xv = *(const float2*)&x[2 * s];
        zx0 = __fmaf_rn(p0, xv.x, zx0); zy0 = __fmaf_rn(p0, xv.y, zy0);
        zx1 = __fmaf_rn(p1, xv.x, zx1); zy1 = __fmaf_rn(p1, xv.y, zy1);
        zx2 = __fmaf_rn(p2, xv.x, zx2); zy2 = __fmaf_rn(p2, xv.y, zy2);
        zx3 = __fmaf_rn(p3, xv.x, zx3); zy3 = __fmaf_rn(p3, xv.y, zy3);
    }
#pragma unroll
    for (int o = 16; o > 0; o >>= 1) {
        s0 += __shfl_xor_sync(FULL, s0, o);  s1 += __shfl_xor_sync(FULL, s1, o);
        s2 += __shfl_xor_sync(FULL, s2, o);  s3 += __shfl_xor_sync(FULL, s3, o);
        zx0 += __shfl_xor_sync(FULL, zx0, o); zx1 += __shfl_xor_sync(FULL, zx1, o);
        zx2 += __shfl_xor_sync(FULL, zx2, o); zx3 += __shfl_xor_sync(FULL, zx3, o);
        zy0 += __shfl_xor_sync(FULL, zy0, o); zy1 += __shfl_xor_sync(FULL, zy1, o);
        zy2 += __shfl_xor_sync(FULL, zy2, o); zy3 += __shfl_xor_sync(FULL, zy3, o);
    }
    float d0 = __fadd_rn(s0, 1e-16f);
    float d1 = __fadd_rn(s1, 1e-16f);
    float d2 = __fadd_rn(s2, 1e-16f);
    float d3 = __fadd_rn(s3, 1e-16f);
    float ZX[4] = {zx0, zx1, zx2, zx3};
    float ZY[4] = {zy0, zy1, zy2, zy3};
    float DD[4] = {d0, d1, d2, d3};

    int c = lane * 4;
    float vals[4];
#pragma unroll
    for (int j = 0; j < 4; j++) {
        int cc = c + j;
        float a = 0.f;
#pragma unroll
        for (int h = 0; h < 4; h++) {
            float w0 = W0[(h * 128 + cc) * 2];
            float w1 = W0[(h * 128 + cc) * 2 + 1];
            float tmp = __fmaf_rn(w0, ZX[h], __fmul_rn(w1, ZY[h]));
            a = __fadd_rn(a, __fdiv_rn(tmp, DD[h]));
        }
        float val = __fmul_rn(a, 0.25f);
        val = __fadd_rn(val, bias[cc]);
        val = elu_acc(val);
        float inv = __frsqrt_rn(__fadd_rn(bnv[cc], 1e-5f));
        val = __fadd_rn(__fmul_rn(__fmul_rn(__fsub_rn(val, bnm[cc]), inv), bng[cc]), bnb[cc]);
        vals[j] = val;
    }
    *(float4*)&g_xa[(size_t)v * 128 + c] = make_float4(vals[0], vals[1], vals[2], vals[3]);
}

// ---------------- layer 1 scores ----------------
__global__ void k_score1(int n) {
    int v = (blockIdx.x * blockDim.x + threadIdx.x) >> 5;
    int lane = threadIdx.x & 31;
    if (v >= n) return;
    float4 xv = *(const float4*)&g_xa[(size_t)v * 128 + lane * 4];
    float sp[4], dp[4];
#pragma unroll
    for (int hd = 0; hd < 4; hd++) {
        float4 wv = *(const float4*)&g_ws[hd * 128 + lane * 4];
        float4 uv = *(const float4*)&g_wd[hd * 128 + lane * 4];
        float s = xv.x * wv.x + xv.y * wv.y + xv.z * wv.z + xv.w * wv.w;
        float d = xv.x * uv.x + xv.y * uv.y + xv.z * uv.z + xv.w * uv.w;
#pragma unroll
        for (int o = 16; o > 0; o >>= 1) {
            s += __shfl_xor_sync(FULL, s, o);
            d += __shfl_xor_sync(FULL, d, o);
        }
        sp[hd] = s;
        dp[hd] = d;
    }
    if (lane == 0) {
        *(float4*)&g_s[v * 4] = make_float4(sp[0], sp[1], sp[2], sp[3]);
        *(float4*)&g_d[v * 4] = make_float4(dp[0], dp[1], dp[2], dp[3]);
    }
}

// ---------------- layer 1: fused softmax + z-aggregate ----------------
__global__ void k_agg1(int n) {
    int v = (blockIdx.x * blockDim.x + threadIdx.x) >> 5;
    int lane = threadIdx.x & 31;
    if (v >= n) return;
    int beg = g_rowptr[v], end = g_rowptr[v + 1];
    float4 dv = *(const float4*)&g_d[v * 4];

    float m0 = -1e30f, m1 = -1e30f, m2 = -1e30f, m3 = -1e30f;
    for (int idx = beg + lane; idx < end; idx += 32) {
        int s = g_csrs[idx];
        float4 sv = *(const float4*)&g_s[s * 4];
        m0 = fmaxf(m0, lrelu(sv.x + dv.x));
        m1 = fmaxf(m1, lrelu(sv.y + dv.y));
        m2 = fmaxf(m2, lrelu(sv.z + dv.z));
        m3 = fmaxf(m3, lrelu(sv.w + dv.w));
    }
#pragma unroll
    for (int o = 16; o > 0; o >>= 1) {
        m0 = fmaxf(m0, __shfl_xor_sync(FULL, m0, o));
        m1 = fmaxf(m1, __shfl_xor_sync(FULL, m1, o));
        m2 = fmaxf(m2, __shfl_xor_sync(FULL, m2, o));
        m3 = fmaxf(m3, __shfl_xor_sync(FULL, m3, o));
    }

    float acc[16];
#pragma unroll
    for (int i = 0; i < 16; i++) acc[i] = 0.f;
    float s0 = 0.f, s1 = 0.f, s2 = 0.f, s3 = 0.f;

    for (int base = beg; base < end; base += 32) {
        int idx = base + lane;
        int sv = 0;
        float p0 = 0.f, p1 = 0.f, p2 = 0.f, p3 = 0.f;
        if (idx < end) {
            sv = g_csrs[idx];
            float4 ss = *(const float4*)&g_s[sv * 4];
            p0 = exp_acc(lrelu(ss.x + dv.x) - m0);
            p1 = exp_acc(lrelu(ss.y + dv.y) - m1);
            p2 = exp_acc(lrelu(ss.z + dv.z) - m2);
            p3 = exp_acc(lrelu(ss.w + dv.w) - m3);
            s0 += p0; s1 += p1; s2 += p2; s3 += p3;
        }
        int cnt = min(32, end - base);
        for (int t = 0; t < cnt; t++) {
            int s = __shfl_sync(FULL, sv, t);
            float q0 = __shfl_sync(FULL, p0, t);
            float q1 = __shfl_sync(FULL, p1, t);
            float q2 = __shfl_sync(FULL, p2, t);
            float q3 = __shfl_sync(FULL, p3, t);
            float4 xv = *(const float4*)&g_xa[(size_t)s * 128 + lane * 4];
            acc[0]  = __fmaf_rn(q0, xv.x, acc[0]);  acc[1]  = __fmaf_rn(q0, xv.y, acc[1]);
            acc[2]  = __fmaf_rn(q0, xv.z, acc[2]);  acc[3]  = __fmaf_rn(q0, xv.w, acc[3]);
            acc[4]  = __fmaf_rn(q1, xv.x, acc[4]);  acc[5]  = __fmaf_rn(q1, xv.y, acc[5]);
            acc[6]  = __fmaf_rn(q1, xv.z, acc[6]);  acc[7]  = __fmaf_rn(q1, xv.w, acc[7]);
            acc[8]  = __fmaf_rn(q2, xv.x, acc[8]);  acc[9]  = __fmaf_rn(q2, xv.y, acc[9]);
            acc[10] = __fmaf_rn(q2, xv.z, acc[10]); acc[11] = __fmaf_rn(q2, xv.w, acc[11]);
            acc[12] = __fmaf_rn(q3, xv.x, acc[12]); acc[13] = __fmaf_rn(q3, xv.y, acc[13]);
            acc[14] = __fmaf_rn(q3, xv.z, acc[14]); acc[15] = __fmaf_rn(q3, xv.w, acc[15]);
        }
    }
#pragma unroll
    for (int o = 16; o > 0; o >>= 1) {
        s0 += __shfl_xor_sync(FULL, s0, o);
        s1 += __shfl_xor_sync(FULL, s1, o);
        s2 += __shfl_xor_sync(FULL, s2, o);
        s3 += __shfl_xor_sync(FULL, s3, o);
    }
    float r0 = __fdiv_rn(1.0f, __fadd_rn(s0, 1e-16f));
    float r1 = __fdiv_rn(1.0f, __fadd_rn(s1, 1e-16f));
    float r2 = __fdiv_rn(1.0f, __fadd_rn(s2, 1e-16f));
    float r3 = __fdiv_rn(1.0f, __fadd_rn(s3, 1e-16f));

    float* zp = &g_z[(size_t)v * 512 + lane * 4];
    *(float4*)&zp[0]   = make_float4(acc[0] * r0,  acc[1] * r0,  acc[2] * r0,  acc[3] * r0);
    *(float4*)&zp[128] = make_float4(acc[4] * r1,  acc[5] * r1,  acc[6] * r1,  acc[7] * r1);
    *(float4*)&zp[256] = make_float4(acc[8] * r2,  acc[9] * r2,  acc[10] * r2, acc[11] * r2);
    *(float4*)&zp[384] = make_float4(acc[12] * r3, acc[13] * r3, acc[14] * r3, acc[15] * r3);
}

// ---------------- layer 1: mma.sync TF32 (3xTF32) GEMM + finalize -> xb ----------------
// xb[v][c] = BN(ELU(0.25 * sum_{K=512} z~[v][k] * Wcat[c][k] + b1[c]))
// Wcat[c][k] with k = h*128+kk -> W1[(h*128+c)*128 + kk]
// CTA: 256 thr, tile M=128 x N=128, K chunks of 32. Warps 2(M) x 4(N), each 64x32.
#define CH 32
#define STR 36
#define SM_AH 0
#define SM_AL (128 * STR)
#define SM_BH (2 * 128 * STR)
#define SM_BL (3 * 128 * STR)
#define MMA_SMEM (4 * 128 * STR * 4)

__global__ void k_gemm_mma(const float* __restrict__ W1, const float* __restrict__ bias,
                           const float* __restrict__ bng, const float* __restrict__ bnb,
                           const float* __restrict__ bnm, const float* __restrict__ bnv,
                           int n) {
    extern __shared__ float sm[];
    int tid = threadIdx.x;
    int wid = tid >> 5, lane = tid & 31;
    int warp_m = wid >> 2;          // 0..1  (64 rows each)
    int warp_n = wid & 3;           // 0..3  (32 cols each)
    int grp = lane >> 2;            // 0..7
    int tig = lane & 3;             // 0..3
    int node0 = blockIdx.x * 128;

    float acc[4][4][4];
#pragma unroll
    for (int mf = 0; mf < 4; mf++)
#pragma unroll
        for (int nf = 0; nf < 4; nf++)
#pragma unroll
            for (int q = 0; q < 4; q++) acc[mf][nf][q] = 0.f;

    for (int ck = 0; ck < 16; ck++) {
        // fill A: z~[node0+row][ck*32 + kl], rows 0..127, kl 0..31
        for (int i = tid; i < 128 * 8; i += 256) {
            int row = i >> 3;
            int kl = (i & 7) * 4;
            int nd = node0 + row;
            float4 v = make_float4(0.f, 0.f, 0.f, 0.f);
            if (nd < n) v = *(const float4*)&g_z[(size_t)nd * 512 + ck * 32 + kl];
            float4 h4, l4;
            h4.x = tf32r(v.x); h4.y = tf32r(v.y); h4.z = tf32r(v.z); h4.w = tf32r(v.w);
            l4.x = v.x - h4.x; l4.y = v.y - h4.y; l4.z = v.z - h4.z; l4.w = v.w - h4.w;
            *(float4*)&sm[SM_AH + row * STR + kl] = h4;
            *(float4*)&sm[SM_AL + row * STR + kl] = l4;
        }
        // fill B: Wcat[c][ck*32 + kl] = W1[(h*128+c)*128 + kk], h=ck>>2, kk=(ck&3)*32+kl
        {
            int h = ck >> 2, kb = (ck & 3) * 32;
            for (int i = tid; i < 128 * 8; i += 256) {
                int row = i >> 3;
                int kl = (i & 7) * 4;
                float4 v = *(const float4*)&W1[(size_t)(h * 128 + row) * 128 + kb + kl];
                float4 h4, l4;
                h4.x = tf32r(v.x); h4.y = tf32r(v.y); h4.z = tf32r(v.z); h4.w = tf32r(v.w);
                l4.x = v.x - h4.x; l4.y = v.y - h4.y; l4.z = v.z - h4.z; l4.w = v.w - h4.w;
                *(float4*)&sm[SM_BH + row * STR + kl] = h4;
                *(float4*)&sm[SM_BL + row * STR + kl] = l4;
            }
        }
        __syncthreads();

#pragma unroll
        for (int k8 = 0; k8 < 4; k8++) {
            int k0 = k8 * 8;
            uint32_t ah[4][4], al[4][4], bh[4][2], bl[4][2];
#pragma unroll
            for (int mf = 0; mf < 4; mf++) {
                int r0 = warp_m * 64 + mf * 16;
                ah[mf][0] = __float_as_uint(sm[SM_AH + (r0 + grp) * STR + k0 + tig]);
                ah[mf][1] = __float_as_uint(sm[SM_AH + (r0 + grp + 8) * STR + k0 + tig]);
                ah[mf][2] = __float_as_uint(sm[SM_AH + (r0 + grp) * STR + k0 + tig + 4]);
                ah[mf][3] = __float_as_uint(sm[SM_AH + (r0 + grp + 8) * STR + k0 + tig + 4]);
                al[mf][0] = __float_as_uint(sm[SM_AL + (r0 + grp) * STR + k0 + tig]);
                al[mf][1] = __float_as_uint(sm[SM_AL + (r0 + grp + 8) * STR + k0 + tig]);
                al[mf][2] = __float_as_uint(sm[SM_AL + (r0 + grp) * STR + k0 + tig + 4]);
                al[mf][3] = __float_as_uint(sm[SM_AL + (r0 + grp + 8) * STR + k0 + tig + 4]);
            }
#pragma unroll
            for (int nf = 0; nf < 4; nf++) {
                int c0 = warp_n * 32 + nf * 8;
                bh[nf][0] = __float_as_uint(sm[SM_BH + (c0 + grp) * STR + k0 + tig]);
                bh[nf][1] = __float_as_uint(sm[SM_BH + (c0 + grp) * STR + k0 + tig + 4]);
                bl[nf][0] = __float_as_uint(sm[SM_BL + (c0 + grp) * STR + k0 + tig]);
                bl[nf][1] = __float_as_uint(sm[SM_BL + (c0 + grp) * STR + k0 + tig + 4]);
            }
#pragma unroll
            for (int mf = 0; mf < 4; mf++)
#pragma unroll
                for (int nf = 0; nf < 4; nf++) {
                    mma_tf32(acc[mf][nf], ah[mf], bh[nf]);
                    mma_tf32(acc[mf][nf], ah[mf], bl[nf]);
                    mma_tf32(acc[mf][nf], al[mf], bh[nf]);
                }
        }
        __syncthreads();
    }

    // epilogue: acc[mf][nf][q] -> (row, col); q0,q1: row=r0+grp, cols c0,c0+1; q2,q3: row+8
#pragma unroll
    for (int mf = 0; mf < 4; mf++) {
        int r0 = node0 + warp_m * 64 + mf * 16 + grp;
#pragma unroll
        for (int half = 0; half < 2; half++) {
            int nd = r0 + half * 8;
            if (nd >= n) continue;
#pragma unroll
            for (int nf = 0; nf < 4; nf++) {
                int c0 = warp_n * 32 + nf * 8 + tig * 2;
                float vv[2];
#pragma unroll
                for (int q = 0; q < 2; q++) {
                    int c = c0 + q;
                    float val = __fmul_rn(acc[mf][nf][half * 2 + q], 0.25f);
                    val = __fadd_rn(val, bias[c]);
                    val = elu_acc(val);
                    float inv = __frsqrt_rn(__fadd_rn(bnv[c], 1e-5f));
                    val = __fadd_rn(__fmul_rn(__fmul_rn(__fsub_rn(val, bnm[c]), inv), bng[c]), bnb[c]);
                    vv[q] = val;
                }
                *(float2*)&g_xb[(size_t)nd * 128 + c0] = make_float2(vv[0], vv[1]);
            }
        }
    }
}

// ---------------- layer 2: fused h2 + scores ----------------
__global__ void k_l2(const float* __restrict__ W, const float* __restrict__ as_,
                     const float* __restrict__ ad_, int n) {
    int v = (blockIdx.x * blockDim.x + threadIdx.x) >> 5;
    int lane = threadIdx.x & 31;
    if (v >= n) return;
    float4 xv = *(const float4*)&g_xb[(size_t)v * 128 + lane * 4];
    float p[3];
#pragma unroll
    for (int o = 0; o < 3; o++) {
        float4 wv = *(const float4*)&W[o * 128 + lane * 4];
        float pp = __fmaf_rn(xv.x, wv.x, __fmaf_rn(xv.y, wv.y, __fmaf_rn(xv.z, wv.z, xv.w * wv.w)));
#pragma unroll
        for (int off = 16; off > 0; off >>= 1) pp += __shfl_xor_sync(FULL, pp, off);
        p[o] = pp;
    }
    if (lane == 0) {
        g_h2[v * 3 + 0] = p[0];
        g_h2[v * 3 + 1] = p[1];
        g_h2[v * 3 + 2] = p[2];
        g_s[v] = __fmaf_rn(p[0], as_[0], __fmaf_rn(p[1], as_[1], p[2] * as_[2]));
        g_d[v] = __fmaf_rn(p[0], ad_[0], __fmaf_rn(p[1], ad_[1], p[2] * ad_[2]));
    }
}

// ---------------- layer 2: softmax + aggregate + ODE epilogue ----------------
__global__ void k_smax2epi(const float* __restrict__ b2,
                           const float* __restrict__ kk, const float* __restrict__ dd,
                           const float* __restrict__ t00, const float* __restrict__ u00,
                           const float* __restrict__ t, float* __restrict__ out, int n) {
    int v = (blockIdx.x * blockDim.x + threadIdx.x) >> 5;
    int lane = threadIdx.x & 31;
    if (v >= n) return;
    int beg = g_rowptr[v], end = g_rowptr[v + 1];
    float sd = g_d[v];

    float mx = -1e30f;
    for (int idx = beg + lane; idx < end; idx += 32)
        mx = fmaxf(mx, lrelu(g_s[g_csrs[idx]] + sd));
#pragma unroll
    for (int o = 16; o > 0; o >>= 1) mx = fmaxf(mx, __shfl_xor_sync(FULL, mx, o));

    float sum = 0.f, a0 = 0.f, a1 = 0.f, a2 = 0.f;
    for (int idx = beg + lane; idx < end; idx += 32) {
        int s = g_csrs[idx];
        float p = exp_acc(lrelu(g_s[s] + sd) - mx);
        sum += p;
        a0 = __fmaf_rn(p, g_h2[s * 3 + 0], a0);
        a1 = __fmaf_rn(p, g_h2[s * 3 + 1], a1);
        a2 = __fmaf_rn(p, g_h2[s * 3 + 2], a2);
    }
#pragma unroll
    for (int o = 16; o > 0; o >>= 1) {
        sum += __shfl_xor_sync(FULL, sum, o);
        a0 += __shfl_xor_sync(FULL, a0, o);
        a1 += __shfl_xor_sync(FULL, a1, o);
        a2 += __shfl_xor_sync(FULL, a2, o);
    }
    if (lane == 0) {
        float denom = __fadd_rn(sum, 1e-16f);
        float ar  = elu_acc(__fadd_rn(__fdiv_rn(a0, denom), b2[0]));
        float gam = elu_acc(__fadd_rn(__fdiv_rn(a1, denom), b2[1]));
        float bet = elu_acc(__fadd_rn(__fdiv_rn(a2, denom), b2[2]));

        float tt = t[v];
        float K = kk[0], D = dd[0], T0 = t00[0], U0 = u00[0];

        float z = __fmul_rn(K, __fsub_rn(__fsub_rn(tt, T0), D));
        float S = __fdiv_rn(1.0f, __fadd_rn(1.0f, exp_acc(-z)));
        float oneMS = __fsub_rn(1.0f, S);

        float eb  = exp_acc(__fmul_rn(-bet, tt));
        float eg  = exp_acc(__fmul_rn(-gam, tt));
        float tmt0 = __fsub_rn(tt, T0);
        float ebs = exp_acc(__fmul_rn(-bet, tmt0));
        float egs = exp_acc(__fmul_rn(-gam, tmt0));
        float ab = __fdiv_rn(ar, bet);
        float ag = __fdiv_rn(ar, gam);

        float tu = __fadd_rn(
                     __fadd_rn(__fmul_rn(__fmul_rn(ab, __fsub_rn(1.0f, eb)), oneMS),
                               __fmul_rn(ab, S)),
                     __fmul_rn(__fsub_rn(__fmul_rn(U0, ebs), ab), S));

        float gmb = __fsub_rn(gam, bet);
        float term1 = __fadd_rn(__fmul_rn(ag, __fsub_rn(1.0f, eg)),
                                __fmul_rn(__fdiv_rn(ar, gmb), __fsub_rn(eg, eb)));
        float term3 = __fmul_rn(__fmul_rn(__fdiv_rn(__fmul_rn(bet, U0), gmb),
                                          __fsub_rn(egs, ebs)), S);
        float ts = __fadd_rn(__fadd_rn(__fmul_rn(term1, oneMS), __fmul_rn(ag, S)), term3);

        out[v] = tu;
        out[n + v] = ts;
    }
}

// ---------------- launch ----------------
extern "C" void kernel_launch(void* const* d_in, const int* in_sizes, int n_in,
                              void* d_out, int out_size) {
    int off = (n_in >= 28) ? 0 : -1;
    const float* x    = (const float*)d_in[0];
    const int*   ei   = (const int*)d_in[1];
    const float* W0   = (const float*)d_in[3 + off];
    const float* as0  = (const float*)d_in[4 + off];
    const float* ad0  = (const float*)d_in[5 + off];
    const float* b0   = (const float*)d_in[6 + off];
    const float* W1   = (const float*)d_in[7 + off];
    const float* as1  = (const float*)d_in[8 + off];
    const float* ad1  = (const float*)d_in[9 + off];
    const float* b1   = (const float*)d_in[10 + off];
    const float* W2   = (const float*)d_in[11 + off];
    const float* as2  = (const float*)d_in[12 + off];
    const float* ad2  = (const float*)d_in[13 + off];
    const float* b2   = (const float*)d_in[14 + off];
    const float* bng0 = (const float*)d_in[15 + off];
    const float* bnb0 = (const float*)d_in[16 + off];
    const float* bnm0 = (const float*)d_in[17 + off];
    const float* bnv0 = (const float*)d_in[18 + off];
    const float* bng1 = (const float*)d_in[19 + off];
    const float* bnb1 = (const float*)d_in[20 + off];
    const float* bnm1 = (const float*)d_in[21 + off];
    const float* bnv1 = (const float*)d_in[22 + off];
    const float* kk   = (const float*)d_in[23 + off];
    const float* dd   = (const float*)d_in[24 + off];
    const float* t00  = (const float*)d_in[25 + off];
    const float* u00  = (const float*)d_in[26 + off];
    const float* t    = (const float*)d_in[27 + off];
    float* out = (float*)d_out;

    int n = in_sizes[0] / 2;
    int e = in_sizes[1] / 2;
    int m = e + n;

    const int B = 256;
    auto nb = [](long long x_, int b) { return (int)((x_ + b - 1) / b); };
    int nwb = nb((long long)n * 32, B);   // warp-per-node grids

    cudaFuncSetAttribute(k_gemm_mma, cudaFuncAttributeMaxDynamicSharedMemorySize, MMA_SMEM);

    // CSR build + attention-vector precompute
    k_zero<<<nb(n, B), B>>>(n);
    k_edges_count<<<nb(m, B), B>>>(ei, e, m);
    k_scan<<<1, 1024>>>(n, m);
    k_fill<<<nb(m, B), B>>>(m);
    k_pre<<<1, 1024>>>(W0, as0, ad0, W1, as1, ad1);

    // ---- layer 0 (h never materialized) ----
    k_score0<<<nb(n, B), B>>>(x, n);
    k_l0agg<<<nwb, B>>>(x, W0, b0, bng0, bnb0, bnm0, bnv0, n);

    // ---- layer 1 (aggregate z first, project after on tensor cores) ----
    k_score1<<<nwb, B>>>(n);
    k_agg1<<<nwb, B>>>(n);
    k_gemm_mma<<<nb(n, 128), 256, MMA_SMEM>>>(W1, b1, bng1, bnb1, bnm1, bnv1, n);

    // ---- layer 2 + epilogue ----
    k_l2<<<nwb, B>>>(W2, as2, ad2, n);
    k_smax2epi<<<nwb, B>>>(b2, kk, dd, t00, u00, t, out, n);
}